// round 6
// baseline (speedup 1.0000x reference)
#include <cuda_runtime.h>
#include <cuda_bf16.h>
#include <cstdint>

#define BB 8
#define CC 64
#define HH 128
#define WW 128
#define HWSZ (HH*WW)
#define KOFF 18

// ---- scratch (no allocations allowed) ----
__device__ float g_offset[BB*KOFF*HWSZ];   // post-PReLU offsets [B,18,H,W]
__device__ float g_atten [BB*CC*HWSZ];     // softmax(conv) [B,64,H,W]
__device__ float g_xt    [BB*HWSZ*CC];     // x transposed to NHWC [B,H,W,C]
__device__ __align__(16) __nv_bfloat16 g_Bimg[576*88]; // B weights [k=576][n=88] bf16
__device__ float g_dummy[1];

typedef unsigned long long u64;

__device__ __forceinline__ u64 pk2(float lo, float hi){
    u64 r; asm("mov.b64 %0, {%1,%2};" : "=l"(r) : "f"(lo), "f"(hi)); return r;
}
__device__ __forceinline__ float2 uf2(u64 v){
    float2 f; asm("mov.b64 {%0,%1}, %2;" : "=f"(f.x), "=f"(f.y) : "l"(v)); return f;
}
__device__ __forceinline__ u64 fma2(u64 a, u64 b, u64 c){
    u64 d; asm("fma.rn.f32x2 %0, %1, %2, %3;" : "=l"(d) : "l"(a), "l"(b), "l"(c)); return d;
}
__device__ __forceinline__ uint32_t smem_to_u32(const void* p){
    uint32_t a;
    asm("{ .reg .u64 t; cvta.to.shared.u64 t, %1; cvt.u32.u64 %0, t; }" : "=r"(a) : "l"(p));
    return a;
}

#define LDSM_X4(r, addr) \
    asm volatile("ldmatrix.sync.aligned.m8n8.x4.shared.b16 {%0,%1,%2,%3}, [%4];" \
        : "=r"((r)[0]),"=r"((r)[1]),"=r"((r)[2]),"=r"((r)[3]) : "r"(addr))
#define LDSM_X2T(r, addr) \
    asm volatile("ldmatrix.sync.aligned.m8n8.x2.trans.shared.b16 {%0,%1}, [%2];" \
        : "=r"((r)[0]),"=r"((r)[1]) : "r"(addr))

__device__ __forceinline__ void mma16816(float* d, const uint32_t* a, const uint32_t* b){
    asm volatile("mma.sync.aligned.m16n8k16.row.col.f32.bf16.bf16.f32 "
        "{%0,%1,%2,%3}, {%4,%5,%6,%7}, {%8,%9}, {%0,%1,%2,%3};"
        : "+f"(d[0]), "+f"(d[1]), "+f"(d[2]), "+f"(d[3])
        : "r"(a[0]), "r"(a[1]), "r"(a[2]), "r"(a[3]), "r"(b[0]), "r"(b[1]));
}

// smem layout for k_convMMA (bytes):
//   [0, 101376)        B weights [576][88] bf16 (row stride 176B, conflict-free)
//   [101376, +56160)   sx: 3 rows x 130 px x 64ch bf16, px stride 144B
//   sD (88x132 f32 = 46464B) aliases the sx region after the mainloop
#define BOFF  0
#define SXOFF 101376
#define SMEMM (101376 + 56160)

// ---------------------------------------------------------------------------
// prepB: B image [k=576][n=88], k = tap*64 + cin; n = oc (64 logits, 18 offs, 6 pad)
// ---------------------------------------------------------------------------
__global__ void k_prepB(const float* __restrict__ cw, const float* __restrict__ offw)
{
    int i = blockIdx.x*256 + threadIdx.x;
    if (i >= 576*88) return;
    int k = i / 88, n = i - k*88;
    int tap = k >> 6, cin = k & 63;
    float v = 0.f;
    if (n < 64)      v = cw [(n*CC + cin)*9 + tap];
    else if (n < 82) v = offw[((n - 64)*CC + cin)*9 + tap];
    g_Bimg[i] = __float2bfloat16(v);
}

__global__ void k_dummy() { if (threadIdx.x == 0) g_dummy[0] = 0.f; }

// ---------------------------------------------------------------------------
// T: transpose x NCHW -> NHWC (g_xt). grid 1024 = (b,h), block 256.
// ---------------------------------------------------------------------------
__global__ __launch_bounds__(256) void k_transpose(const float* __restrict__ x)
{
    __shared__ float s[64][129];
    int t = threadIdx.x;
    int b = blockIdx.x >> 7, h = blockIdx.x & 127;
    const float* xb = x + b*CC*HWSZ + h*WW;
    for (int i = t; i < 64*128; i += 256) {
        int c = i >> 7, w = i & 127;
        s[c][w] = xb[c*HWSZ + w];
    }
    __syncthreads();
    float* ob = g_xt + (b*HH + h)*WW*CC;
    for (int i = t; i < 64*128; i += 256) {
        int w = i >> 6, c = i & 63;
        ob[w*CC + c] = s[c][w];
    }
}

// ---------------------------------------------------------------------------
// convMMA: per (b,h) row, im2col GEMM on HMMA (mma.sync m16n8k16 bf16).
// grid 1024 = (b,h), block 256 = 8 warps x 16 px rows.
// ---------------------------------------------------------------------------
__global__ __launch_bounds__(256, 1) void k_convMMA(
    const float* __restrict__ offb, const float* __restrict__ pa_)
{
    extern __shared__ char smem[];
    uint32_t sb = smem_to_u32(smem);
    int t = threadIdx.x, wid = t >> 5, lane = t & 31;
    int b = blockIdx.x >> 7, h = blockIdx.x & 127;

    // ---- copy B weights into smem ----
    {
        const uint4* src = (const uint4*)g_Bimg;
        uint4* dst = (uint4*)(smem + BOFF);
        for (int i = t; i < 101376/16; i += 256) dst[i] = src[i];
    }

    // ---- stage x rows h-1..h+1 as bf16, NHWC, padded (130 px, stride 144B) ----
    for (int i = t; i < 3*130*32; i += 256) {
        int rp = i >> 5, cp = i & 31;
        int r = rp / 130, pxp = rp - r*130;
        int y = h + r - 1, xc = pxp - 1;
        float2 v = make_float2(0.f, 0.f);
        if (y >= 0 && y < HH && xc >= 0 && xc < WW)
            v = *(const float2*)(g_xt + ((size_t)(b*HH + y)*WW + xc)*CC + cp*2);
        uint32_t p;
        asm("cvt.rn.satfinite.bf16x2.f32 %0, %1, %2;" : "=r"(p) : "f"(v.y), "f"(v.x));
        *(uint32_t*)(smem + SXOFF + rp*144 + cp*4) = p;
    }
    __syncthreads();

    // ---- mainloop: 9 taps x 4 k16-steps x 11 n-tiles ----
    float acc[11][4];
    #pragma unroll
    for (int nt = 0; nt < 11; nt++)
        #pragma unroll
        for (int j = 0; j < 4; j++) acc[nt][j] = 0.f;

    uint32_t l15  = lane & 15;
    uint32_t hi16 = (uint32_t)(lane >> 4) * 16;
    uint32_t sxa  = sb + SXOFF;
    uint32_t ba   = sb + BOFF;

    #pragma unroll 1
    for (int tap = 0; tap < 9; tap++) {
        int ky = tap / 3, kx = tap - ky*3;
        uint32_t rowA = sxa + (uint32_t)(ky*130 + kx + wid*16 + (int)l15)*144 + hi16;
        uint32_t rowB = ba + (uint32_t)(tap*64 + (int)l15)*176;
        #pragma unroll
        for (int s = 0; s < 4; s++) {
            uint32_t a[4];
            LDSM_X4(a, rowA + s*32);
            uint32_t bA = rowB + (uint32_t)s*16*176;
            #pragma unroll
            for (int nt = 0; nt < 11; nt++) {
                uint32_t bf[2];
                LDSM_X2T(bf, bA + nt*16);
                mma16816(acc[nt], a, bf);
            }
        }
    }

    // ---- fragments -> sD[oc][px] (aliases sx region; sx dead now) ----
    __syncthreads();
    float* sD = (float*)(smem + SXOFF);
    {
        int n0 = (lane & 3)*2;
        int px = wid*16 + (lane >> 2);
        #pragma unroll
        for (int nt = 0; nt < 11; nt++) {
            int n = nt*8 + n0;
            sD[n*132 + px]           = acc[nt][0];
            sD[(n + 1)*132 + px]     = acc[nt][1];
            sD[n*132 + px + 8]       = acc[nt][2];
            sD[(n + 1)*132 + px + 8] = acc[nt][3];
        }
    }
    __syncthreads();

    // ---- epilogue ----
    float pa = pa_[0];
    for (int oc = wid; oc < 82; oc += 8) {
        float v[4];
        #pragma unroll
        for (int j = 0; j < 4; j++) v[j] = sD[oc*132 + lane + 32*j];
        if (oc < 64) {
            float m = fmaxf(fmaxf(v[0], v[1]), fmaxf(v[2], v[3]));
            #pragma unroll
            for (int s = 16; s > 0; s >>= 1)
                m = fmaxf(m, __shfl_xor_sync(0xffffffffu, m, s));
            float e[4]; float sum = 0.f;
            #pragma unroll
            for (int j = 0; j < 4; j++) { e[j] = __expf(v[j] - m); sum += e[j]; }
            #pragma unroll
            for (int s = 16; s > 0; s >>= 1)
                sum += __shfl_xor_sync(0xffffffffu, sum, s);
            float inv = 1.0f / sum;
            int base = ((b*CC + oc)*HH + h)*WW + lane;
            #pragma unroll
            for (int j = 0; j < 4; j++) g_atten[base + 32*j] = e[j]*inv;
        } else {
            int o2 = oc - 64;
            float bo = offb[o2];
            int base = ((b*KOFF + o2)*HH + h)*WW + lane;
            #pragma unroll
            for (int j = 0; j < 4; j++) {
                float u = v[j] + bo;
                g_offset[base + 32*j] = u >= 0.f ? u : pa*u;
            }
        }
    }
}

// ---------------------------------------------------------------------------
// D: deformable grouped conv, ALL 8 groups per block for L1 line reuse.
//    grid 1024 = (b,h), block 512 = 64 wp (2 px) x 8 groups.
//    out = atten*feat + x fused.
// ---------------------------------------------------------------------------
__global__ __launch_bounds__(512) void k_deformD(
    const float* __restrict__ x, const float* __restrict__ dw,
    const float* __restrict__ db, float* __restrict__ out)
{
    extern __shared__ float smB[];
    float* soff = smB;                          // 18*128 floats (9216B)
    u64*   swd  = (u64*)(smB + KOFF*WW);        // 64oc*8ci*9 dup'd (36864B)

    int t = threadIdx.x;
    int b = blockIdx.x >> 7, h = blockIdx.x & 127;

    for (int i = t; i < KOFF*WW; i += 512)
        soff[i] = g_offset[(b*KOFF + (i >> 7))*HWSZ + h*WW + (i & 127)];
    for (int i = t; i < CC*8*9; i += 512) { float v = dw[i]; swd[i] = pk2(v, v); }
    __syncthreads();

    int wp = t & 63, g = t >> 6;
    int w0 = wp*2;

    u64 acc[8];
    #pragma unroll
    for (int o = 0; o < 8; o++) { float bo = db[g*8 + o]; acc[o] = pk2(bo, bo); }

    const float* xtb = g_xt + (size_t)b*HWSZ*CC + g*8;

    #pragma unroll 1
    for (int k = 0; k < 9; k++) {
        int ky = k / 3, kx = k - ky*3;
        float s[2][8];
        #pragma unroll
        for (int p = 0; p < 2; p++) {
            int w = w0 + p;
            float dy = soff[(2*k)*WW + w];
            float dx = soff[(2*k + 1)*WW + w];
            float ys = (float)(h - 1 + ky) + dy;
            float xs = (float)(w - 1 + kx) + dx;
            float yf = floorf(ys), xf = floorf(xs);
            float ay = ys - yf, ax = xs - xf;
            int iy0 = (int)yf, ix0 = (int)xf;
            float my0 = (iy0 >= 0  && iy0 < HH)     ? 1.f : 0.f;
            float my1 = (iy0 >= -1 && iy0 + 1 < HH) ? 1.f : 0.f;
            float mx0 = (ix0 >= 0  && ix0 < WW)     ? 1.f : 0.f;
            float mx1 = (ix0 >= -1 && ix0 + 1 < WW) ? 1.f : 0.f;
            int cy0 = min(max(iy0, 0), HH - 1), cy1 = min(max(iy0 + 1, 0), HH - 1);
            int cx0 = min(max(ix0, 0), WW - 1), cx1 = min(max(ix0 + 1, 0), WW - 1);
            float c00 = (1.f - ay)*(1.f - ax)*my0*mx0;
            float c01 = (1.f - ay)*ax*my0*mx1;
            float c10 = ay*(1.f - ax)*my1*mx0;
            float c11 = ay*ax*my1*mx1;
            const float* pA = xtb + (cy0*WW + cx0)*CC;
            const float* pB = xtb + (cy0*WW + cx1)*CC;
            const float* pC = xtb + (cy1*WW + cx0)*CC;
            const float* pD = xtb + (cy1*WW + cx1)*CC;
            float4 A0 = *(const float4*)pA,       A1 = *(const float4*)(pA + 4);
            float4 B0 = *(const float4*)pB,       B1 = *(const float4*)(pB + 4);
            float4 C0 = *(const float4*)pC,       C1 = *(const float4*)(pC + 4);
            float4 D0 = *(const float4*)pD,       D1 = *(const float4*)(pD + 4);
            s[p][0] = c00*A0.x + c01*B0.x + c10*C0.x + c11*D0.x;
            s[p][1] = c00*A0.y + c01*B0.y + c10*C0.y + c11*D0.y;
            s[p][2] = c00*A0.z + c01*B0.z + c10*C0.z + c11*D0.z;
            s[p][3] = c00*A0.w + c01*B0.w + c10*C0.w + c11*D0.w;
            s[p][4] = c00*A1.x + c01*B1.x + c10*C1.x + c11*D1.x;
            s[p][5] = c00*A1.y + c01*B1.y + c10*C1.y + c11*D1.y;
            s[p][6] = c00*A1.z + c01*B1.z + c10*C1.z + c11*D1.z;
            s[p][7] = c00*A1.w + c01*B1.w + c10*C1.w + c11*D1.w;
        }
        const u64* wk = swd + (g*64)*9 + k;
        #pragma unroll
        for (int ci = 0; ci < 8; ci++) {
            u64 av = pk2(s[0][ci], s[1][ci]);
            #pragma unroll
            for (int o = 0; o < 8; o++)
                acc[o] = fma2(wk[(o*8 + ci)*9], av, acc[o]);
        }
    }

    #pragma unroll
    for (int o = 0; o < 8; o++) {
        int oc = g*8 + o;
        float2 f = uf2(acc[o]);
        int base = ((b*CC + oc)*HH + h)*WW + w0;
        float2 at = *(const float2*)(g_atten + base);
        float2 xv = *(const float2*)(x + base);
        float2 ov = make_float2(fmaf(at.x, f.x, xv.x), fmaf(at.y, f.y, xv.y));
        *(float2*)(out + base) = ov;
    }
}

extern "C" void kernel_launch(void* const* d_in, const int* in_sizes, int n_in,
                              void* d_out, int out_size)
{
    const float* x    = (const float*)d_in[0];
    const float* offw = (const float*)d_in[1];
    const float* offb = (const float*)d_in[2];
    const float* pa   = (const float*)d_in[3];
    const float* dw   = (const float*)d_in[4];
    const float* db   = (const float*)d_in[5];
    const float* cw   = (const float*)d_in[6];
    float* out = (float*)d_out;

    const int smemD = KOFF*WW*4 + CC*8*9*8;              // 46080

    cudaFuncSetAttribute(k_convMMA, cudaFuncAttributeMaxDynamicSharedMemorySize, SMEMM);
    cudaFuncSetAttribute(k_deformD, cudaFuncAttributeMaxDynamicSharedMemorySize, smemD);

    k_prepB<<<198, 256>>>(cw, offw);
    k_transpose<<<1024, 256>>>(x);
    k_convMMA<<<1024, 256, SMEMM>>>(offb, pa);
    k_dummy<<<1, 32>>>();
    k_deformD<<<1024, 512, smemD>>>(x, dw, db, out);   // 5th launch -> ncu capture
}

// round 7
// speedup vs baseline: 1.9018x; 1.9018x over previous
#include <cuda_runtime.h>
#include <cuda_bf16.h>
#include <cstdint>

#define BB 8
#define CC 64
#define HH 128
#define WW 128
#define HWSZ (HH*WW)
#define KOFF 18

// ---- scratch (no allocations allowed) ----
__device__ float g_offset[BB*KOFF*HWSZ];   // post-PReLU offsets [B,18,H,W]
__device__ float g_atten [BB*CC*HWSZ];     // softmax(conv) [B,64,H,W]
__device__ float g_xt    [BB*HWSZ*CC];     // x transposed to NHWC [B,H,W,C]
__device__ __align__(16) __nv_bfloat16 g_Bimg[576*88]; // B weights [k=576][n=88] bf16

typedef unsigned long long u64;

__device__ __forceinline__ uint32_t smem_to_u32(const void* p){
    uint32_t a;
    asm("{ .reg .u64 t; cvta.to.shared.u64 t, %1; cvt.u32.u64 %0, t; }" : "=r"(a) : "l"(p));
    return a;
}

#define LDSM_X4(r, addr) \
    asm volatile("ldmatrix.sync.aligned.m8n8.x4.shared.b16 {%0,%1,%2,%3}, [%4];" \
        : "=r"((r)[0]),"=r"((r)[1]),"=r"((r)[2]),"=r"((r)[3]) : "r"(addr))
#define LDSM_X2T(r, addr) \
    asm volatile("ldmatrix.sync.aligned.m8n8.x2.trans.shared.b16 {%0,%1}, [%2];" \
        : "=r"((r)[0]),"=r"((r)[1]) : "r"(addr))

__device__ __forceinline__ void mma16816(float* d, const uint32_t* a, const uint32_t* b){
    asm volatile("mma.sync.aligned.m16n8k16.row.col.f32.bf16.bf16.f32 "
        "{%0,%1,%2,%3}, {%4,%5,%6,%7}, {%8,%9}, {%0,%1,%2,%3};"
        : "+f"(d[0]), "+f"(d[1]), "+f"(d[2]), "+f"(d[3])
        : "r"(a[0]), "r"(a[1]), "r"(a[2]), "r"(a[3]), "r"(b[0]), "r"(b[1]));
}

// smem layout for k_convMMA (bytes)
#define BOFF  0
#define SXOFF 101376
#define SMEMM (101376 + 56160)

// ---------------------------------------------------------------------------
// prepB: B image [k=576][n=88]
// ---------------------------------------------------------------------------
__global__ void k_prepB(const float* __restrict__ cw, const float* __restrict__ offw)
{
    int i = blockIdx.x*256 + threadIdx.x;
    if (i >= 576*88) return;
    int k = i / 88, n = i - k*88;
    int tap = k >> 6, cin = k & 63;
    float v = 0.f;
    if (n < 64)      v = cw [(n*CC + cin)*9 + tap];
    else if (n < 82) v = offw[((n - 64)*CC + cin)*9 + tap];
    g_Bimg[i] = __float2bfloat16(v);
}

// ---------------------------------------------------------------------------
// T: transpose x NCHW -> NHWC (g_xt). grid 1024 = (b,h), block 256.
// ---------------------------------------------------------------------------
__global__ __launch_bounds__(256) void k_transpose(const float* __restrict__ x)
{
    __shared__ float s[64][129];
    int t = threadIdx.x;
    int b = blockIdx.x >> 7, h = blockIdx.x & 127;
    const float* xb = x + b*CC*HWSZ + h*WW;
    for (int i = t; i < 64*128; i += 256) {
        int c = i >> 7, w = i & 127;
        s[c][w] = xb[c*HWSZ + w];
    }
    __syncthreads();
    float* ob = g_xt + (b*HH + h)*WW*CC;
    for (int i = t; i < 64*128; i += 256) {
        int w = i >> 6, c = i & 63;
        ob[w*CC + c] = s[c][w];
    }
}

// ---------------------------------------------------------------------------
// convMMA: per (b,h) row, im2col GEMM on HMMA (mma.sync m16n8k16 bf16).
// ---------------------------------------------------------------------------
__global__ __launch_bounds__(256, 1) void k_convMMA(
    const float* __restrict__ offb, const float* __restrict__ pa_)
{
    extern __shared__ char smem[];
    uint32_t sb = smem_to_u32(smem);
    int t = threadIdx.x, wid = t >> 5, lane = t & 31;
    int b = blockIdx.x >> 7, h = blockIdx.x & 127;

    {
        const uint4* src = (const uint4*)g_Bimg;
        uint4* dst = (uint4*)(smem + BOFF);
        for (int i = t; i < 101376/16; i += 256) dst[i] = src[i];
    }

    for (int i = t; i < 3*130*32; i += 256) {
        int rp = i >> 5, cp = i & 31;
        int r = rp / 130, pxp = rp - r*130;
        int y = h + r - 1, xc = pxp - 1;
        float2 v = make_float2(0.f, 0.f);
        if (y >= 0 && y < HH && xc >= 0 && xc < WW)
            v = *(const float2*)(g_xt + ((size_t)(b*HH + y)*WW + xc)*CC + cp*2);
        uint32_t p;
        asm("cvt.rn.satfinite.bf16x2.f32 %0, %1, %2;" : "=r"(p) : "f"(v.y), "f"(v.x));
        *(uint32_t*)(smem + SXOFF + rp*144 + cp*4) = p;
    }
    __syncthreads();

    float acc[11][4];
    #pragma unroll
    for (int nt = 0; nt < 11; nt++)
        #pragma unroll
        for (int j = 0; j < 4; j++) acc[nt][j] = 0.f;

    uint32_t l15  = lane & 15;
    uint32_t hi16 = (uint32_t)(lane >> 4) * 16;
    uint32_t sxa  = sb + SXOFF;
    uint32_t ba   = sb + BOFF;

    #pragma unroll 1
    for (int tap = 0; tap < 9; tap++) {
        int ky = tap / 3, kx = tap - ky*3;
        uint32_t rowA = sxa + (uint32_t)(ky*130 + kx + wid*16 + (int)l15)*144 + hi16;
        uint32_t rowB = ba + (uint32_t)(tap*64 + (int)l15)*176;
        #pragma unroll
        for (int s = 0; s < 4; s++) {
            uint32_t a[4];
            LDSM_X4(a, rowA + s*32);
            uint32_t bA = rowB + (uint32_t)s*16*176;
            #pragma unroll
            for (int nt = 0; nt < 11; nt++) {
                uint32_t bf[2];
                LDSM_X2T(bf, bA + nt*16);
                mma16816(acc[nt], a, bf);
            }
        }
    }

    __syncthreads();
    float* sD = (float*)(smem + SXOFF);
    {
        int n0 = (lane & 3)*2;
        int px = wid*16 + (lane >> 2);
        #pragma unroll
        for (int nt = 0; nt < 11; nt++) {
            int n = nt*8 + n0;
            sD[n*132 + px]           = acc[nt][0];
            sD[(n + 1)*132 + px]     = acc[nt][1];
            sD[n*132 + px + 8]       = acc[nt][2];
            sD[(n + 1)*132 + px + 8] = acc[nt][3];
        }
    }
    __syncthreads();

    float pa = pa_[0];
    for (int oc = wid; oc < 82; oc += 8) {
        float v[4];
        #pragma unroll
        for (int j = 0; j < 4; j++) v[j] = sD[oc*132 + lane + 32*j];
        if (oc < 64) {
            float m = fmaxf(fmaxf(v[0], v[1]), fmaxf(v[2], v[3]));
            #pragma unroll
            for (int s = 16; s > 0; s >>= 1)
                m = fmaxf(m, __shfl_xor_sync(0xffffffffu, m, s));
            float e[4]; float sum = 0.f;
            #pragma unroll
            for (int j = 0; j < 4; j++) { e[j] = __expf(v[j] - m); sum += e[j]; }
            #pragma unroll
            for (int s = 16; s > 0; s >>= 1)
                sum += __shfl_xor_sync(0xffffffffu, sum, s);
            float inv = 1.0f / sum;
            int base = ((b*CC + oc)*HH + h)*WW + lane;
            #pragma unroll
            for (int j = 0; j < 4; j++) g_atten[base + 32*j] = e[j]*inv;
        } else {
            int o2 = oc - 64;
            float bo = offb[o2];
            int base = ((b*KOFF + o2)*HH + h)*WW + lane;
            #pragma unroll
            for (int j = 0; j < 4; j++) {
                float u = v[j] + bo;
                g_offset[base + 32*j] = u >= 0.f ? u : pa*u;
            }
        }
    }
}

// ---------------------------------------------------------------------------
// E: deformable grouped conv, wavefront-minimal gather.
//    grid 4096 = (b,h,quarter); block 512: lane = pxl*16 + g*2 + half.
//    16 consecutive lanes cover one pixel's full 256B channel line.
//    Each thread: 4 channels (half group), 1 px; partner-half combined by shfl.
//    out = atten*feat + x fused, coalesced via smem staging.
// ---------------------------------------------------------------------------
__global__ __launch_bounds__(512) void k_deformE(
    const float* __restrict__ x, const float* __restrict__ dw,
    const float* __restrict__ db, float* __restrict__ out)
{
    extern __shared__ float smE[];
    float* soff  = smE;                 // [18][32]            2304 B
    float* sw    = smE + 18*32;         // [16 gh][9 tap][36]  20736 B
    float* sfeat = sw + 16*9*36;        // [64 oc][36 px]      9216 B

    int t = threadIdx.x;
    int b  = blockIdx.x >> 9;
    int h  = (blockIdx.x >> 2) & 127;
    int q  = blockIdx.x & 3;
    int px0 = q*32;

    // offsets for this 32-px span
    for (int i = t; i < 18*32; i += 512)
        soff[i] = g_offset[(b*KOFF + (i >> 5))*HWSZ + h*WW + px0 + (i & 31)];
    // weights: sw[(gh*9+tap)*36 + ci4*8 + o] = dw[(g*8+o)][half*4+ci4][tap]
    for (int i = t; i < 16*9*32; i += 512) {
        int gh = i / 288; int rem = i - gh*288;
        int tap = rem >> 5; int j = rem & 31;
        int ci4 = j >> 3, o = j & 7;
        int g = gh >> 1, half = gh & 1;
        sw[(gh*9 + tap)*36 + j] = dw[((g*8 + o)*8 + half*4 + ci4)*9 + tap];
    }
    __syncthreads();

    int pl = t >> 4, gh = t & 15;
    int g = gh >> 1, half = gh & 1;
    int w = px0 + pl;

    float acc[8];
    #pragma unroll
    for (int o = 0; o < 8; o++) acc[o] = half ? 0.f : db[g*8 + o];

    const float* xg = g_xt + (size_t)b*HWSZ*CC + g*8 + half*4;

    #pragma unroll 1
    for (int k = 0; k < 9; k++) {
        int ky = k / 3, kx = k - ky*3;
        float dy = soff[(2*k)*32 + pl];
        float dx = soff[(2*k + 1)*32 + pl];
        float ys = (float)(h - 1 + ky) + dy;
        float xs = (float)(w - 1 + kx) + dx;
        float yf = floorf(ys), xf = floorf(xs);
        float ay = ys - yf, ax = xs - xf;
        int iy0 = (int)yf, ix0 = (int)xf;
        float my0 = (iy0 >= 0  && iy0 < HH)     ? 1.f : 0.f;
        float my1 = (iy0 >= -1 && iy0 + 1 < HH) ? 1.f : 0.f;
        float mx0 = (ix0 >= 0  && ix0 < WW)     ? 1.f : 0.f;
        float mx1 = (ix0 >= -1 && ix0 + 1 < WW) ? 1.f : 0.f;
        int cy0 = min(max(iy0, 0), HH - 1), cy1 = min(max(iy0 + 1, 0), HH - 1);
        int cx0 = min(max(ix0, 0), WW - 1), cx1 = min(max(ix0 + 1, 0), WW - 1);
        float c00 = (1.f - ay)*(1.f - ax)*my0*mx0;
        float c01 = (1.f - ay)*ax*my0*mx1;
        float c10 = ay*(1.f - ax)*my1*mx0;
        float c11 = ay*ax*my1*mx1;
        // 4 corner loads: 16 consecutive lanes -> one 256B pixel line each
        float4 vA = *(const float4*)(xg + (cy0*WW + cx0)*CC);
        float4 vB = *(const float4*)(xg + (cy0*WW + cx1)*CC);
        float4 vC = *(const float4*)(xg + (cy1*WW + cx0)*CC);
        float4 vD = *(const float4*)(xg + (cy1*WW + cx1)*CC);
        float s0 = c00*vA.x + c01*vB.x + c10*vC.x + c11*vD.x;
        float s1 = c00*vA.y + c01*vB.y + c10*vC.y + c11*vD.y;
        float s2 = c00*vA.z + c01*vB.z + c10*vC.z + c11*vD.z;
        float s3 = c00*vA.w + c01*vB.w + c10*vC.w + c11*vD.w;
        const float* wt = sw + (gh*9 + k)*36;
        float4 w0v, w1v;
        w0v = *(const float4*)(wt + 0);  w1v = *(const float4*)(wt + 4);
        acc[0] = fmaf(w0v.x, s0, acc[0]); acc[1] = fmaf(w0v.y, s0, acc[1]);
        acc[2] = fmaf(w0v.z, s0, acc[2]); acc[3] = fmaf(w0v.w, s0, acc[3]);
        acc[4] = fmaf(w1v.x, s0, acc[4]); acc[5] = fmaf(w1v.y, s0, acc[5]);
        acc[6] = fmaf(w1v.z, s0, acc[6]); acc[7] = fmaf(w1v.w, s0, acc[7]);
        w0v = *(const float4*)(wt + 8);  w1v = *(const float4*)(wt + 12);
        acc[0] = fmaf(w0v.x, s1, acc[0]); acc[1] = fmaf(w0v.y, s1, acc[1]);
        acc[2] = fmaf(w0v.z, s1, acc[2]); acc[3] = fmaf(w0v.w, s1, acc[3]);
        acc[4] = fmaf(w1v.x, s1, acc[4]); acc[5] = fmaf(w1v.y, s1, acc[5]);
        acc[6] = fmaf(w1v.z, s1, acc[6]); acc[7] = fmaf(w1v.w, s1, acc[7]);
        w0v = *(const float4*)(wt + 16); w1v = *(const float4*)(wt + 20);
        acc[0] = fmaf(w0v.x, s2, acc[0]); acc[1] = fmaf(w0v.y, s2, acc[1]);
        acc[2] = fmaf(w0v.z, s2, acc[2]); acc[3] = fmaf(w0v.w, s2, acc[3]);
        acc[4] = fmaf(w1v.x, s2, acc[4]); acc[5] = fmaf(w1v.y, s2, acc[5]);
        acc[6] = fmaf(w1v.z, s2, acc[6]); acc[7] = fmaf(w1v.w, s2, acc[7]);
        w0v = *(const float4*)(wt + 24); w1v = *(const float4*)(wt + 28);
        acc[0] = fmaf(w0v.x, s3, acc[0]); acc[1] = fmaf(w0v.y, s3, acc[1]);
        acc[2] = fmaf(w0v.z, s3, acc[2]); acc[3] = fmaf(w0v.w, s3, acc[3]);
        acc[4] = fmaf(w1v.x, s3, acc[4]); acc[5] = fmaf(w1v.y, s3, acc[5]);
        acc[6] = fmaf(w1v.z, s3, acc[6]); acc[7] = fmaf(w1v.w, s3, acc[7]);
    }

    // combine halves (lane xor 1 = same px,g, other half) and stage to smem
    #pragma unroll
    for (int o = 0; o < 8; o++)
        acc[o] += __shfl_xor_sync(0xffffffffu, acc[o], 1);
    if (half == 0) {
        #pragma unroll
        for (int o = 0; o < 8; o++)
            sfeat[(g*8 + o)*36 + pl] = acc[o];
    }
    __syncthreads();

    // coalesced epilogue: out = atten*feat + x, one float4 per thread
    {
        int oc = t >> 3, p4 = t & 7;
        float4 f = *(const float4*)(sfeat + oc*36 + p4*4);
        int base = ((b*CC + oc)*HH + h)*WW + px0 + p4*4;
        float4 at = *(const float4*)(g_atten + base);
        float4 xv = *(const float4*)(x + base);
        float4 ov = make_float4(fmaf(at.x, f.x, xv.x), fmaf(at.y, f.y, xv.y),
                                fmaf(at.z, f.z, xv.z), fmaf(at.w, f.w, xv.w));
        *(float4*)(out + base) = ov;
    }
}

extern "C" void kernel_launch(void* const* d_in, const int* in_sizes, int n_in,
                              void* d_out, int out_size)
{
    const float* x    = (const float*)d_in[0];
    const float* offw = (const float*)d_in[1];
    const float* offb = (const float*)d_in[2];
    const float* pa   = (const float*)d_in[3];
    const float* dw   = (const float*)d_in[4];
    const float* db   = (const float*)d_in[5];
    const float* cw   = (const float*)d_in[6];
    float* out = (float*)d_out;

    const int smemE = (18*32 + 16*9*36 + 64*36)*4;       // 32256

    cudaFuncSetAttribute(k_convMMA, cudaFuncAttributeMaxDynamicSharedMemorySize, SMEMM);
    cudaFuncSetAttribute(k_deformE, cudaFuncAttributeMaxDynamicSharedMemorySize, smemE);

    k_prepB<<<198, 256>>>(cw, offw);
    k_transpose<<<1024, 256>>>(x);
    k_convMMA<<<1024, 256, SMEMM>>>(offb, pa);
    k_deformE<<<4096, 512, smemE>>>(x, dw, db, out);
}

// round 9
// speedup vs baseline: 2.0253x; 1.0649x over previous
#include <cuda_runtime.h>
#include <cuda_bf16.h>
#include <cstdint>

#define BB 8
#define CC 64
#define HH 128
#define WW 128
#define HWSZ (HH*WW)
#define KOFF 18

// ---- scratch (no allocations allowed) ----
__device__ float g_offset[BB*KOFF*HWSZ];   // post-PReLU offsets [B,18,H,W]
__device__ float g_atten [BB*CC*HWSZ];     // softmax(conv) [B,64,H,W]
__device__ float g_xt    [BB*HWSZ*CC];     // x transposed to NHWC [B,H,W,C]
__device__ __align__(16) __nv_bfloat16 g_Bimg[576*88]; // B weights [k=576][n=88] bf16

typedef unsigned long long u64;

__device__ __forceinline__ uint32_t smem_to_u32(const void* p){
    uint32_t a;
    asm("{ .reg .u64 t; cvta.to.shared.u64 t, %1; cvt.u32.u64 %0, t; }" : "=r"(a) : "l"(p));
    return a;
}

#define LDSM_X4(r, addr) \
    asm volatile("ldmatrix.sync.aligned.m8n8.x4.shared.b16 {%0,%1,%2,%3}, [%4];" \
        : "=r"((r)[0]),"=r"((r)[1]),"=r"((r)[2]),"=r"((r)[3]) : "r"(addr))
#define LDSM_X2T(r, addr) \
    asm volatile("ldmatrix.sync.aligned.m8n8.x2.trans.shared.b16 {%0,%1}, [%2];" \
        : "=r"((r)[0]),"=r"((r)[1]) : "r"(addr))

__device__ __forceinline__ void mma16816(float* d, const uint32_t* a, const uint32_t* b){
    asm volatile("mma.sync.aligned.m16n8k16.row.col.f32.bf16.bf16.f32 "
        "{%0,%1,%2,%3}, {%4,%5,%6,%7}, {%8,%9}, {%0,%1,%2,%3};"
        : "+f"(d[0]), "+f"(d[1]), "+f"(d[2]), "+f"(d[3])
        : "r"(a[0]), "r"(a[1]), "r"(a[2]), "r"(a[3]), "r"(b[0]), "r"(b[1]));
}

// smem layout for k_convMMA2 (bytes)
#define BOFF  0
#define SXOFF 101376
#define SMEMM (101376 + 74880)

// ---------------------------------------------------------------------------
__global__ void k_prepB(const float* __restrict__ cw, const float* __restrict__ offw)
{
    int i = blockIdx.x*256 + threadIdx.x;
    if (i >= 576*88) return;
    int k = i / 88, n = i - k*88;
    int tap = k >> 6, cin = k & 63;
    float v = 0.f;
    if (n < 64)      v = cw [(n*CC + cin)*9 + tap];
    else if (n < 82) v = offw[((n - 64)*CC + cin)*9 + tap];
    g_Bimg[i] = __float2bfloat16(v);
}

// ---------------------------------------------------------------------------
// T: transpose x NCHW -> NHWC. grid 2048 = (b,h,chalf), block 256.
// ---------------------------------------------------------------------------
__global__ __launch_bounds__(256) void k_transpose(const float* __restrict__ x)
{
    __shared__ float s[32][129];
    int t = threadIdx.x;
    int b = blockIdx.x >> 8, h = (blockIdx.x >> 1) & 127, ch = blockIdx.x & 1;
    const float* xb = x + (b*CC + ch*32)*HWSZ + h*WW;
    for (int i = t; i < 32*32; i += 256) {
        int c = i >> 5, wq = i & 31;
        float4 v = *(const float4*)(xb + c*HWSZ + wq*4);
        s[c][wq*4 + 0] = v.x; s[c][wq*4 + 1] = v.y;
        s[c][wq*4 + 2] = v.z; s[c][wq*4 + 3] = v.w;
    }
    __syncthreads();
    float* ob = g_xt + (size_t)(b*HH + h)*WW*CC + ch*32;
    for (int i = t; i < 128*32; i += 256) {
        int w = i >> 5, c = i & 31;
        ob[w*CC + c] = s[c][w];
    }
}

// ---------------------------------------------------------------------------
// convMMA2: 2 output rows per block (M=256, N=88, K=576 bf16 HMMA).
// ---------------------------------------------------------------------------
__global__ __launch_bounds__(256) void k_convMMA2(
    const float* __restrict__ offb, const float* __restrict__ pa_)
{
    extern __shared__ char smem[];
    uint32_t sb = smem_to_u32(smem);
    int t = threadIdx.x, wid = t >> 5, lane = t & 31;
    int b = blockIdx.x >> 6, h2 = blockIdx.x & 63;
    int h0 = h2*2;

    {
        const uint4* src = (const uint4*)g_Bimg;
        uint4* dst = (uint4*)(smem + BOFF);
        for (int i = t; i < 101376/16; i += 256) dst[i] = src[i];
    }

    for (int i = t; i < 4*130*32; i += 256) {
        int rp = i >> 5, cp = i & 31;
        int r = rp / 130, pxp = rp - r*130;
        int y = h0 + r - 1, xc = pxp - 1;
        float2 v = make_float2(0.f, 0.f);
        if (y >= 0 && y < HH && xc >= 0 && xc < WW)
            v = *(const float2*)(g_xt + ((size_t)(b*HH + y)*WW + xc)*CC + cp*2);
        uint32_t p;
        asm("cvt.rn.satfinite.bf16x2.f32 %0, %1, %2;" : "=r"(p) : "f"(v.y), "f"(v.x));
        *(uint32_t*)(smem + SXOFF + rp*144 + cp*4) = p;
    }
    __syncthreads();

    float acc[2][11][4];
    #pragma unroll
    for (int a = 0; a < 2; a++)
        #pragma unroll
        for (int nt = 0; nt < 11; nt++)
            #pragma unroll
            for (int j = 0; j < 4; j++) acc[a][nt][j] = 0.f;

    uint32_t l15  = lane & 15;
    uint32_t hi16 = (uint32_t)(lane >> 4) * 16;
    uint32_t sxa  = sb + SXOFF;
    uint32_t ba   = sb + BOFF;
    int orow = wid >> 2, pxb = (wid & 3)*32;

    #pragma unroll 1
    for (int tap = 0; tap < 9; tap++) {
        int ky = tap / 3, kx = tap - ky*3;
        uint32_t rowA0 = sxa + (uint32_t)((orow + ky)*130 + pxb + (int)l15 + kx)*144 + hi16;
        uint32_t rowB  = ba + (uint32_t)(tap*64 + (int)l15)*176;
        #pragma unroll
        for (int s = 0; s < 4; s++) {
            uint32_t a0[4], a1[4];
            LDSM_X4(a0, rowA0 + s*32);
            LDSM_X4(a1, rowA0 + 16*144 + s*32);
            uint32_t bA = rowB + (uint32_t)s*16*176;
            #pragma unroll
            for (int nt = 0; nt < 11; nt++) {
                uint32_t bf[2];
                LDSM_X2T(bf, bA + nt*16);
                mma16816(acc[0][nt], a0, bf);
                mma16816(acc[1][nt], a1, bf);
            }
        }
    }

    __syncthreads();
    float* sD = (float*)(smem);
    {
        int n0 = (lane & 3)*2;
        int m0 = wid*32 + (lane >> 2);
        #pragma unroll
        for (int a = 0; a < 2; a++) {
            int m = m0 + a*16;
            #pragma unroll
            for (int nt = 0; nt < 11; nt++) {
                int n = nt*8 + n0;
                sD[n*264 + m]           = acc[a][nt][0];
                sD[(n + 1)*264 + m]     = acc[a][nt][1];
                sD[n*264 + m + 8]       = acc[a][nt][2];
                sD[(n + 1)*264 + m + 8] = acc[a][nt][3];
            }
        }
    }
    __syncthreads();

    float pa = pa_[0];
    for (int idx = wid; idx < 164; idx += 8) {
        int oc = idx >> 1, row = idx & 1;
        int h = h0 + row;
        float v[4];
        #pragma unroll
        for (int j = 0; j < 4; j++) v[j] = sD[oc*264 + row*128 + lane + 32*j];
        if (oc < 64) {
            float m = fmaxf(fmaxf(v[0], v[1]), fmaxf(v[2], v[3]));
            #pragma unroll
            for (int s = 16; s > 0; s >>= 1)
                m = fmaxf(m, __shfl_xor_sync(0xffffffffu, m, s));
            float e[4]; float sum = 0.f;
            #pragma unroll
            for (int j = 0; j < 4; j++) { e[j] = __expf(v[j] - m); sum += e[j]; }
            #pragma unroll
            for (int s = 16; s > 0; s >>= 1)
                sum += __shfl_xor_sync(0xffffffffu, sum, s);
            float inv = 1.0f / sum;
            int base = ((b*CC + oc)*HH + h)*WW + lane;
            #pragma unroll
            for (int j = 0; j < 4; j++) g_atten[base + 32*j] = e[j]*inv;
        } else {
            int o2 = oc - 64;
            float bo = offb[o2];
            int base = ((b*KOFF + o2)*HH + h)*WW + lane;
            #pragma unroll
            for (int j = 0; j < 4; j++) {
                float u = v[j] + bo;
                g_offset[base + 32*j] = u >= 0.f ? u : pa*u;
            }
        }
    }
}

// ---------------------------------------------------------------------------
// F: deformable grouped conv, wavefront-minimal gather, 2 px per thread,
//    per-tap weights cached in registers. SWS=36 (16B-aligned rows).
// ---------------------------------------------------------------------------
#define SWS 36   // sw row stride (36*4=144B, 16B-aligned for float4)
#define SFS 36   // sfeat row stride
__global__ __launch_bounds__(256, 2) void k_deformF(
    const float* __restrict__ x, const float* __restrict__ dw,
    const float* __restrict__ db, float* __restrict__ out)
{
    extern __shared__ float smF[];
    float* soff  = smF;                   // [18][32]
    float* sw    = smF + 18*32;           // [16 gh][9 tap][SWS]
    float* sfeat = sw + 16*9*SWS;         // [64 oc][SFS]

    int t = threadIdx.x;
    int b  = blockIdx.x >> 9;
    int h  = (blockIdx.x >> 2) & 127;
    int q  = blockIdx.x & 3;
    int px0 = q*32;

    for (int i = t; i < 18*32; i += 256)
        soff[i] = g_offset[(b*KOFF + (i >> 5))*HWSZ + h*WW + px0 + (i & 31)];
    for (int i = t; i < 16*9*32; i += 256) {
        int gh = i / 288; int rem = i - gh*288;
        int tap = rem >> 5; int j = rem & 31;
        int ci4 = j >> 3, o = j & 7;
        int g = gh >> 1, half = gh & 1;
        sw[(gh*9 + tap)*SWS + j] = dw[((g*8 + o)*8 + half*4 + ci4)*9 + tap];
    }
    __syncthreads();

    int pl = t >> 4, gh = t & 15;
    int g = gh >> 1, half = gh & 1;
    int wA = px0 + pl, wB = px0 + pl + 16;

    float acc0[8], acc1[8];
    #pragma unroll
    for (int o = 0; o < 8; o++) {
        float bo = half ? 0.f : db[g*8 + o];
        acc0[o] = bo; acc1[o] = bo;
    }

    const float* xg = g_xt + (size_t)b*HWSZ*CC + g*8 + half*4;

    #pragma unroll 1
    for (int k = 0; k < 9; k++) {
        int ky = k / 3, kx = k - ky*3;
        const float* wt = sw + (gh*9 + k)*SWS;
        float4 W0 = *(const float4*)(wt + 0),  W1 = *(const float4*)(wt + 4);
        float4 W2 = *(const float4*)(wt + 8),  W3 = *(const float4*)(wt + 12);
        float4 W4 = *(const float4*)(wt + 16), W5 = *(const float4*)(wt + 20);
        float4 W6 = *(const float4*)(wt + 24), W7 = *(const float4*)(wt + 28);

        #pragma unroll
        for (int p = 0; p < 2; p++) {
            int w = p ? wB : wA;
            float* acc = p ? acc1 : acc0;
            int plo = p ? (pl + 16) : pl;
            float dy = soff[(2*k)*32 + plo];
            float dx = soff[(2*k + 1)*32 + plo];
            float ys = (float)(h - 1 + ky) + dy;
            float xs = (float)(w - 1 + kx) + dx;
            float yf = floorf(ys), xf = floorf(xs);
            float ay = ys - yf, ax = xs - xf;
            int iy0 = (int)yf, ix0 = (int)xf;
            float my0 = (iy0 >= 0  && iy0 < HH)     ? 1.f : 0.f;
            float my1 = (iy0 >= -1 && iy0 + 1 < HH) ? 1.f : 0.f;
            float mx0 = (ix0 >= 0  && ix0 < WW)     ? 1.f : 0.f;
            float mx1 = (ix0 >= -1 && ix0 + 1 < WW) ? 1.f : 0.f;
            int cy0 = min(max(iy0, 0), HH - 1), cy1 = min(max(iy0 + 1, 0), HH - 1);
            int cx0 = min(max(ix0, 0), WW - 1), cx1 = min(max(ix0 + 1, 0), WW - 1);
            float c00 = (1.f - ay)*(1.f - ax)*my0*mx0;
            float c01 = (1.f - ay)*ax*my0*mx1;
            float c10 = ay*(1.f - ax)*my1*mx0;
            float c11 = ay*ax*my1*mx1;
            float4 vA = *(const float4*)(xg + (cy0*WW + cx0)*CC);
            float4 vB = *(const float4*)(xg + (cy0*WW + cx1)*CC);
            float4 vC = *(const float4*)(xg + (cy1*WW + cx0)*CC);
            float4 vD = *(const float4*)(xg + (cy1*WW + cx1)*CC);
            float s0 = c00*vA.x + c01*vB.x + c10*vC.x + c11*vD.x;
            float s1 = c00*vA.y + c01*vB.y + c10*vC.y + c11*vD.y;
            float s2 = c00*vA.z + c01*vB.z + c10*vC.z + c11*vD.z;
            float s3 = c00*vA.w + c01*vB.w + c10*vC.w + c11*vD.w;
            acc[0] = fmaf(W0.x, s0, acc[0]); acc[1] = fmaf(W0.y, s0, acc[1]);
            acc[2] = fmaf(W0.z, s0, acc[2]); acc[3] = fmaf(W0.w, s0, acc[3]);
            acc[4] = fmaf(W1.x, s0, acc[4]); acc[5] = fmaf(W1.y, s0, acc[5]);
            acc[6] = fmaf(W1.z, s0, acc[6]); acc[7] = fmaf(W1.w, s0, acc[7]);
            acc[0] = fmaf(W2.x, s1, acc[0]); acc[1] = fmaf(W2.y, s1, acc[1]);
            acc[2] = fmaf(W2.z, s1, acc[2]); acc[3] = fmaf(W2.w, s1, acc[3]);
            acc[4] = fmaf(W3.x, s1, acc[4]); acc[5] = fmaf(W3.y, s1, acc[5]);
            acc[6] = fmaf(W3.z, s1, acc[6]); acc[7] = fmaf(W3.w, s1, acc[7]);
            acc[0] = fmaf(W4.x, s2, acc[0]); acc[1] = fmaf(W4.y, s2, acc[1]);
            acc[2] = fmaf(W4.z, s2, acc[2]); acc[3] = fmaf(W4.w, s2, acc[3]);
            acc[4] = fmaf(W5.x, s2, acc[4]); acc[5] = fmaf(W5.y, s2, acc[5]);
            acc[6] = fmaf(W5.z, s2, acc[6]); acc[7] = fmaf(W5.w, s2, acc[7]);
            acc[0] = fmaf(W6.x, s3, acc[0]); acc[1] = fmaf(W6.y, s3, acc[1]);
            acc[2] = fmaf(W6.z, s3, acc[2]); acc[3] = fmaf(W6.w, s3, acc[3]);
            acc[4] = fmaf(W7.x, s3, acc[4]); acc[5] = fmaf(W7.y, s3, acc[5]);
            acc[6] = fmaf(W7.z, s3, acc[6]); acc[7] = fmaf(W7.w, s3, acc[7]);
        }
    }

    #pragma unroll
    for (int o = 0; o < 8; o++) {
        acc0[o] += __shfl_xor_sync(0xffffffffu, acc0[o], 1);
        acc1[o] += __shfl_xor_sync(0xffffffffu, acc1[o], 1);
    }
    if (half == 0) {
        #pragma unroll
        for (int o = 0; o < 8; o++) {
            sfeat[(g*8 + o)*SFS + pl]      = acc0[o];
            sfeat[(g*8 + o)*SFS + pl + 16] = acc1[o];
        }
    }
    __syncthreads();

    #pragma unroll
    for (int it = 0; it < 2; it++) {
        int idx = t + it*256;
        int oc = idx >> 3, p4 = idx & 7;
        float4 f = *(const float4*)(sfeat + oc*SFS + p4*4);
        int base = ((b*CC + oc)*HH + h)*WW + px0 + p4*4;
        float4 at = *(const float4*)(g_atten + base);
        float4 xv = *(const float4*)(x + base);
        float4 ov = make_float4(fmaf(at.x, f.x, xv.x), fmaf(at.y, f.y, xv.y),
                                fmaf(at.z, f.z, xv.z), fmaf(at.w, f.w, xv.w));
        *(float4*)(out + base) = ov;
    }
}

extern "C" void kernel_launch(void* const* d_in, const int* in_sizes, int n_in,
                              void* d_out, int out_size)
{
    const float* x    = (const float*)d_in[0];
    const float* offw = (const float*)d_in[1];
    const float* offb = (const float*)d_in[2];
    const float* pa   = (const float*)d_in[3];
    const float* dw   = (const float*)d_in[4];
    const float* db   = (const float*)d_in[5];
    const float* cw   = (const float*)d_in[6];
    float* out = (float*)d_out;

    const int smemF = (18*32 + 16*9*SWS + 64*SFS)*4;

    cudaFuncSetAttribute(k_convMMA2, cudaFuncAttributeMaxDynamicSharedMemorySize, SMEMM);
    cudaFuncSetAttribute(k_deformF,  cudaFuncAttributeMaxDynamicSharedMemorySize, smemF);

    k_prepB<<<198, 256>>>(cw, offw);
    k_transpose<<<2048, 256>>>(x);
    k_convMMA2<<<512, 256, SMEMM>>>(offb, pa);
    k_deformF<<<4096, 256, smemF>>>(x, dw, db, out);
}

// round 10
// speedup vs baseline: 2.1233x; 1.0484x over previous
#include <cuda_runtime.h>
#include <cuda_bf16.h>
#include <cstdint>

#define BB 8
#define CC 64
#define HH 128
#define WW 128
#define HWSZ (HH*WW)
#define KOFF 18

// ---- scratch (no allocations allowed) ----
__device__ float g_offset[BB*KOFF*HWSZ];   // post-PReLU offsets [B,18,H,W]
__device__ float g_atten [BB*CC*HWSZ];     // softmax(conv) [B,64,H,W]
__device__ __align__(16) __nv_bfloat16 g_xtb[BB*HWSZ*CC];  // x NHWC bf16
__device__ __align__(16) __nv_bfloat16 g_Bimg[576*88];     // B weights [k=576][n=88] bf16

typedef unsigned long long u64;

__device__ __forceinline__ uint32_t smem_to_u32(const void* p){
    uint32_t a;
    asm("{ .reg .u64 t; cvta.to.shared.u64 t, %1; cvt.u32.u64 %0, t; }" : "=r"(a) : "l"(p));
    return a;
}
__device__ __forceinline__ float bfLO(uint32_t u){ return __uint_as_float(u << 16); }
__device__ __forceinline__ float bfHI(uint32_t u){ return __uint_as_float(u & 0xffff0000u); }

#define LDSM_X4(r, addr) \
    asm volatile("ldmatrix.sync.aligned.m8n8.x4.shared.b16 {%0,%1,%2,%3}, [%4];" \
        : "=r"((r)[0]),"=r"((r)[1]),"=r"((r)[2]),"=r"((r)[3]) : "r"(addr))
#define LDSM_X2T(r, addr) \
    asm volatile("ldmatrix.sync.aligned.m8n8.x2.trans.shared.b16 {%0,%1}, [%2];" \
        : "=r"((r)[0]),"=r"((r)[1]) : "r"(addr))

__device__ __forceinline__ void mma16816(float* d, const uint32_t* a, const uint32_t* b){
    asm volatile("mma.sync.aligned.m16n8k16.row.col.f32.bf16.bf16.f32 "
        "{%0,%1,%2,%3}, {%4,%5,%6,%7}, {%8,%9}, {%0,%1,%2,%3};"
        : "+f"(d[0]), "+f"(d[1]), "+f"(d[2]), "+f"(d[3])
        : "r"(a[0]), "r"(a[1]), "r"(a[2]), "r"(a[3]), "r"(b[0]), "r"(b[1]));
}

// convMMA4 smem (bytes): [0,56160) sx (3x130 px rows, stride 144B bf16);
// [56160, +22528) B double buffer (2 x 64 k-rows x 176B).
// sD (88x132 f32 = 46464B) aliases [0,46464) after mainloop.
#define SB4   56160
#define SMEM4 (56160 + 22528)

// ---------------------------------------------------------------------------
__global__ void k_prepB(const float* __restrict__ cw, const float* __restrict__ offw)
{
    int i = blockIdx.x*256 + threadIdx.x;
    if (i >= 576*88) return;
    int k = i / 88, n = i - k*88;
    int tap = k >> 6, cin = k & 63;
    float v = 0.f;
    if (n < 64)      v = cw [(n*CC + cin)*9 + tap];
    else if (n < 82) v = offw[((n - 64)*CC + cin)*9 + tap];
    g_Bimg[i] = __float2bfloat16(v);
}

// ---------------------------------------------------------------------------
// T: transpose x NCHW f32 -> NHWC bf16 (g_xtb). grid 2048 = (b,h,chalf).
// ---------------------------------------------------------------------------
__global__ __launch_bounds__(256) void k_transpose(const float* __restrict__ x)
{
    __shared__ float s[32][129];
    int t = threadIdx.x;
    int b = blockIdx.x >> 8, h = (blockIdx.x >> 1) & 127, ch = blockIdx.x & 1;
    const float* xb = x + (b*CC + ch*32)*HWSZ + h*WW;
    for (int i = t; i < 32*32; i += 256) {
        int c = i >> 5, wq = i & 31;
        float4 v = *(const float4*)(xb + c*HWSZ + wq*4);
        s[c][wq*4 + 0] = v.x; s[c][wq*4 + 1] = v.y;
        s[c][wq*4 + 2] = v.z; s[c][wq*4 + 3] = v.w;
    }
    __syncthreads();
    __nv_bfloat16* ob = g_xtb + (size_t)(b*HH + h)*WW*CC + ch*32;
    for (int i = t; i < 128*16; i += 256) {
        int w = i >> 4, cp = i & 15;
        uint32_t p;
        asm("cvt.rn.satfinite.bf16x2.f32 %0, %1, %2;"
            : "=r"(p) : "f"(s[cp*2 + 1][w]), "f"(s[cp*2][w]));
        *(uint32_t*)(ob + w*CC + cp*2) = p;
    }
}

// ---------------------------------------------------------------------------
// convMMA4: per (b,h) row, M=128, N=88, K=576 bf16 HMMA; warp = 16 px;
// B streamed per tap (double buffer) -> small smem -> 2 blocks/SM.
// ---------------------------------------------------------------------------
__global__ __launch_bounds__(256, 2) void k_convMMA4(
    const float* __restrict__ offb, const float* __restrict__ pa_)
{
    extern __shared__ char smem[];
    uint32_t sb = smem_to_u32(smem);
    int t = threadIdx.x, wid = t >> 5, lane = t & 31;
    int b = blockIdx.x >> 7, h = blockIdx.x & 127;

    // stage sx: rows h-1..h+1, 130 px (pad), 64ch bf16, stride 144B — pure copy
    for (int i = t; i < 3*130*8; i += 256) {
        int rp = i >> 3, q = i & 7;
        int r = rp / 130, pxp = rp - r*130;
        int y = h + r - 1, xc = pxp - 1;
        uint4 v = make_uint4(0u, 0u, 0u, 0u);
        if (y >= 0 && y < HH && xc >= 0 && xc < WW)
            v = *(const uint4*)(g_xtb + ((size_t)(b*HH + y)*WW + xc)*CC + q*8);
        *(uint4*)(smem + rp*144 + q*16) = v;
    }
    // preload B tap 0
    {
        const uint4* s0 = (const uint4*)g_Bimg;
        uint4* d0 = (uint4*)(smem + SB4);
        for (int i = t; i < 704; i += 256) d0[i] = s0[i];
    }
    __syncthreads();

    float acc[11][4];
    #pragma unroll
    for (int nt = 0; nt < 11; nt++)
        #pragma unroll
        for (int j = 0; j < 4; j++) acc[nt][j] = 0.f;

    uint32_t l15  = lane & 15;
    uint32_t hi16 = (uint32_t)(lane >> 4) * 16;

    #pragma unroll 1
    for (int tap = 0; tap < 9; tap++) {
        int ky = tap / 3, kx = tap - ky*3;
        uint32_t bbase = sb + SB4 + (uint32_t)(tap & 1)*11264;
        // prefetch next tap's B chunk into the other buffer
        if (tap < 8) {
            const uint4* srcB = (const uint4*)g_Bimg + (tap + 1)*704;
            uint4* dstB = (uint4*)(smem + SB4 + ((tap + 1) & 1)*11264);
            for (int i = t; i < 704; i += 256) dstB[i] = srcB[i];
        }
        uint32_t rowA = sb + (uint32_t)(ky*130 + kx + wid*16 + (int)l15)*144 + hi16;
        uint32_t rowB = bbase + l15*176;
        #pragma unroll
        for (int s = 0; s < 4; s++) {
            uint32_t a[4];
            LDSM_X4(a, rowA + s*32);
            uint32_t bA = rowB + (uint32_t)s*16*176;
            #pragma unroll
            for (int nt = 0; nt < 11; nt++) {
                uint32_t bf[2];
                LDSM_X2T(bf, bA + nt*16);
                mma16816(acc[nt], a, bf);
            }
        }
        __syncthreads();
    }

    // fragments -> sD[oc][px] (aliases sx; dead now)
    float* sD = (float*)(smem);
    {
        int n0 = (lane & 3)*2;
        int px = wid*16 + (lane >> 2);
        #pragma unroll
        for (int nt = 0; nt < 11; nt++) {
            int n = nt*8 + n0;
            sD[n*132 + px]           = acc[nt][0];
            sD[(n + 1)*132 + px]     = acc[nt][1];
            sD[n*132 + px + 8]       = acc[nt][2];
            sD[(n + 1)*132 + px + 8] = acc[nt][3];
        }
    }
    __syncthreads();

    float pa = pa_[0];
    for (int oc = wid; oc < 82; oc += 8) {
        float v[4];
        #pragma unroll
        for (int j = 0; j < 4; j++) v[j] = sD[oc*132 + lane + 32*j];
        if (oc < 64) {
            float m = fmaxf(fmaxf(v[0], v[1]), fmaxf(v[2], v[3]));
            #pragma unroll
            for (int s = 16; s > 0; s >>= 1)
                m = fmaxf(m, __shfl_xor_sync(0xffffffffu, m, s));
            float e[4]; float sum = 0.f;
            #pragma unroll
            for (int j = 0; j < 4; j++) { e[j] = __expf(v[j] - m); sum += e[j]; }
            #pragma unroll
            for (int s = 16; s > 0; s >>= 1)
                sum += __shfl_xor_sync(0xffffffffu, sum, s);
            float inv = 1.0f / sum;
            int base = ((b*CC + oc)*HH + h)*WW + lane;
            #pragma unroll
            for (int j = 0; j < 4; j++) g_atten[base + 32*j] = e[j]*inv;
        } else {
            int o2 = oc - 64;
            float bo = offb[o2];
            int base = ((b*KOFF + o2)*HH + h)*WW + lane;
            #pragma unroll
            for (int j = 0; j < 4; j++) {
                float u = v[j] + bo;
                g_offset[base + 32*j] = u >= 0.f ? u : pa*u;
            }
        }
    }
}

// ---------------------------------------------------------------------------
// G: deformable grouped conv, bf16 gather (128B pixel line = 1 L1 line),
//    2 px per thread, per-tap weights in registers. out = atten*feat + x.
//    grid 4096 = (b,h,quarter); block 256: t = pl*16 + gh.
// ---------------------------------------------------------------------------
#define SWS 36
#define SFS 36
__global__ __launch_bounds__(256, 2) void k_deformG(
    const float* __restrict__ x, const float* __restrict__ dw,
    const float* __restrict__ db, float* __restrict__ out)
{
    extern __shared__ float smF[];
    float* soff  = smF;                   // [18][32]
    float* sw    = smF + 18*32;           // [16 gh][9 tap][SWS]
    float* sfeat = sw + 16*9*SWS;         // [64 oc][SFS]

    int t = threadIdx.x;
    int b  = blockIdx.x >> 9;
    int h  = (blockIdx.x >> 2) & 127;
    int q  = blockIdx.x & 3;
    int px0 = q*32;

    for (int i = t; i < 18*32; i += 256)
        soff[i] = g_offset[(b*KOFF + (i >> 5))*HWSZ + h*WW + px0 + (i & 31)];
    for (int i = t; i < 16*9*32; i += 256) {
        int gh = i / 288; int rem = i - gh*288;
        int tap = rem >> 5; int j = rem & 31;
        int ci4 = j >> 3, o = j & 7;
        int g = gh >> 1, half = gh & 1;
        sw[(gh*9 + tap)*SWS + j] = dw[((g*8 + o)*8 + half*4 + ci4)*9 + tap];
    }
    __syncthreads();

    int pl = t >> 4, gh = t & 15;
    int g = gh >> 1, half = gh & 1;

    float acc0[8], acc1[8];
    #pragma unroll
    for (int o = 0; o < 8; o++) {
        float bo = half ? 0.f : db[g*8 + o];
        acc0[o] = bo; acc1[o] = bo;
    }

    const __nv_bfloat16* xgb = g_xtb + (size_t)b*HWSZ*CC + g*8 + half*4;

    #pragma unroll 1
    for (int k = 0; k < 9; k++) {
        int ky = k / 3, kx = k - ky*3;
        const float* wt = sw + (gh*9 + k)*SWS;
        float4 W0 = *(const float4*)(wt + 0),  W1 = *(const float4*)(wt + 4);
        float4 W2 = *(const float4*)(wt + 8),  W3 = *(const float4*)(wt + 12);
        float4 W4 = *(const float4*)(wt + 16), W5 = *(const float4*)(wt + 20);
        float4 W6 = *(const float4*)(wt + 24), W7 = *(const float4*)(wt + 28);

        #pragma unroll
        for (int p = 0; p < 2; p++) {
            int plo = pl + p*16;
            int w = px0 + plo;
            float* acc = p ? acc1 : acc0;
            float dy = soff[(2*k)*32 + plo];
            float dx = soff[(2*k + 1)*32 + plo];
            float ys = (float)(h - 1 + ky) + dy;
            float xs = (float)(w - 1 + kx) + dx;
            float yf = floorf(ys), xf = floorf(xs);
            float ay = ys - yf, ax = xs - xf;
            int iy0 = (int)yf, ix0 = (int)xf;
            float my0 = (iy0 >= 0  && iy0 < HH)     ? 1.f : 0.f;
            float my1 = (iy0 >= -1 && iy0 + 1 < HH) ? 1.f : 0.f;
            float mx0 = (ix0 >= 0  && ix0 < WW)     ? 1.f : 0.f;
            float mx1 = (ix0 >= -1 && ix0 + 1 < WW) ? 1.f : 0.f;
            int cy0 = min(max(iy0, 0), HH - 1), cy1 = min(max(iy0 + 1, 0), HH - 1);
            int cx0 = min(max(ix0, 0), WW - 1), cx1 = min(max(ix0 + 1, 0), WW - 1);
            float c00 = (1.f - ay)*(1.f - ax)*my0*mx0;
            float c01 = (1.f - ay)*ax*my0*mx1;
            float c10 = ay*(1.f - ax)*my1*mx0;
            float c11 = ay*ax*my1*mx1;
            uint2 A = *(const uint2*)(xgb + (cy0*WW + cx0)*CC);
            uint2 Bv = *(const uint2*)(xgb + (cy0*WW + cx1)*CC);
            uint2 Cv = *(const uint2*)(xgb + (cy1*WW + cx0)*CC);
            uint2 D = *(const uint2*)(xgb + (cy1*WW + cx1)*CC);
            float s0 = c00*bfLO(A.x) + c01*bfLO(Bv.x) + c10*bfLO(Cv.x) + c11*bfLO(D.x);
            float s1 = c00*bfHI(A.x) + c01*bfHI(Bv.x) + c10*bfHI(Cv.x) + c11*bfHI(D.x);
            float s2 = c00*bfLO(A.y) + c01*bfLO(Bv.y) + c10*bfLO(Cv.y) + c11*bfLO(D.y);
            float s3 = c00*bfHI(A.y) + c01*bfHI(Bv.y) + c10*bfHI(Cv.y) + c11*bfHI(D.y);
            acc[0] = fmaf(W0.x, s0, acc[0]); acc[1] = fmaf(W0.y, s0, acc[1]);
            acc[2] = fmaf(W0.z, s0, acc[2]); acc[3] = fmaf(W0.w, s0, acc[3]);
            acc[4] = fmaf(W1.x, s0, acc[4]); acc[5] = fmaf(W1.y, s0, acc[5]);
            acc[6] = fmaf(W1.z, s0, acc[6]); acc[7] = fmaf(W1.w, s0, acc[7]);
            acc[0] = fmaf(W2.x, s1, acc[0]); acc[1] = fmaf(W2.y, s1, acc[1]);
            acc[2] = fmaf(W2.z, s1, acc[2]); acc[3] = fmaf(W2.w, s1, acc[3]);
            acc[4] = fmaf(W3.x, s1, acc[4]); acc[5] = fmaf(W3.y, s1, acc[5]);
            acc[6] = fmaf(W3.z, s1, acc[6]); acc[7] = fmaf(W3.w, s1, acc[7]);
            acc[0] = fmaf(W4.x, s2, acc[0]); acc[1] = fmaf(W4.y, s2, acc[1]);
            acc[2] = fmaf(W4.z, s2, acc[2]); acc[3] = fmaf(W4.w, s2, acc[3]);
            acc[4] = fmaf(W5.x, s2, acc[4]); acc[5] = fmaf(W5.y, s2, acc[5]);
            acc[6] = fmaf(W5.z, s2, acc[6]); acc[7] = fmaf(W5.w, s2, acc[7]);
            acc[0] = fmaf(W6.x, s3, acc[0]); acc[1] = fmaf(W6.y, s3, acc[1]);
            acc[2] = fmaf(W6.z, s3, acc[2]); acc[3] = fmaf(W6.w, s3, acc[3]);
            acc[4] = fmaf(W7.x, s3, acc[4]); acc[5] = fmaf(W7.y, s3, acc[5]);
            acc[6] = fmaf(W7.z, s3, acc[6]); acc[7] = fmaf(W7.w, s3, acc[7]);
        }
    }

    #pragma unroll
    for (int o = 0; o < 8; o++) {
        acc0[o] += __shfl_xor_sync(0xffffffffu, acc0[o], 1);
        acc1[o] += __shfl_xor_sync(0xffffffffu, acc1[o], 1);
    }
    if (half == 0) {
        #pragma unroll
        for (int o = 0; o < 8; o++) {
            sfeat[(g*8 + o)*SFS + pl]      = acc0[o];
            sfeat[(g*8 + o)*SFS + pl + 16] = acc1[o];
        }
    }
    __syncthreads();

    #pragma unroll
    for (int it = 0; it < 2; it++) {
        int idx = t + it*256;
        int oc = idx >> 3, p4 = idx & 7;
        float4 f = *(const float4*)(sfeat + oc*SFS + p4*4);
        int base = ((b*CC + oc)*HH + h)*WW + px0 + p4*4;
        float4 at = *(const float4*)(g_atten + base);
        float4 xv = *(const float4*)(x + base);
        float4 ov = make_float4(fmaf(at.x, f.x, xv.x), fmaf(at.y, f.y, xv.y),
                                fmaf(at.z, f.z, xv.z), fmaf(at.w, f.w, xv.w));
        *(float4*)(out + base) = ov;
    }
}

extern "C" void kernel_launch(void* const* d_in, const int* in_sizes, int n_in,
                              void* d_out, int out_size)
{
    const float* x    = (const float*)d_in[0];
    const float* offw = (const float*)d_in[1];
    const float* offb = (const float*)d_in[2];
    const float* pa   = (const float*)d_in[3];
    const float* dw   = (const float*)d_in[4];
    const float* db   = (const float*)d_in[5];
    const float* cw   = (const float*)d_in[6];
    float* out = (float*)d_out;

    const int smemG = (18*32 + 16*9*SWS + 64*SFS)*4;

    cudaFuncSetAttribute(k_convMMA4, cudaFuncAttributeMaxDynamicSharedMemorySize, SMEM4);
    cudaFuncSetAttribute(k_deformG,  cudaFuncAttributeMaxDynamicSharedMemorySize, smemG);

    k_prepB<<<198, 256>>>(cw, offw);
    k_transpose<<<2048, 256>>>(x);
    k_convMMA4<<<1024, 256, SMEM4>>>(offb, pa);
    k_deformG<<<4096, 256, smemG>>>(x, dw, db, out);
}

// round 11
// speedup vs baseline: 2.4668x; 1.1618x over previous
#include <cuda_runtime.h>
#include <cuda_bf16.h>
#include <cstdint>

#define BB 8
#define CC 64
#define HH 128
#define WW 128
#define HWSZ (HH*WW)
#define KOFF 18

// ---- scratch (no allocations allowed) ----
__device__ float g_offset[BB*KOFF*HWSZ];   // post-PReLU offsets [B,18,H,W]
__device__ float g_atten [BB*CC*HWSZ];     // softmax(conv) [B,64,H,W]
__device__ __align__(16) __nv_bfloat16 g_xtb[BB*HWSZ*CC];  // x NHWC bf16
__device__ __align__(16) __nv_bfloat16 g_Bimg[576*88];     // B weights [k=576][n=88] bf16

typedef unsigned long long u64;

__device__ __forceinline__ uint32_t smem_to_u32(const void* p){
    uint32_t a;
    asm("{ .reg .u64 t; cvta.to.shared.u64 t, %1; cvt.u32.u64 %0, t; }" : "=r"(a) : "l"(p));
    return a;
}
__device__ __forceinline__ float bfLO(uint32_t u){ return __uint_as_float(u << 16); }
__device__ __forceinline__ float bfHI(uint32_t u){ return __uint_as_float(u & 0xffff0000u); }
__device__ __forceinline__ u64 pk2(float lo, float hi){
    u64 r; asm("mov.b64 %0, {%1,%2};" : "=l"(r) : "f"(lo), "f"(hi)); return r;
}
__device__ __forceinline__ float2 uf2(u64 v){
    float2 f; asm("mov.b64 {%0,%1}, %2;" : "=f"(f.x), "=f"(f.y) : "l"(v)); return f;
}
__device__ __forceinline__ u64 fma2(u64 a, u64 b, u64 c){
    u64 d; asm("fma.rn.f32x2 %0, %1, %2, %3;" : "=l"(d) : "l"(a), "l"(b), "l"(c)); return d;
}

#define LDSM_X4(r, addr) \
    asm volatile("ldmatrix.sync.aligned.m8n8.x4.shared.b16 {%0,%1,%2,%3}, [%4];" \
        : "=r"((r)[0]),"=r"((r)[1]),"=r"((r)[2]),"=r"((r)[3]) : "r"(addr))
#define LDSM_X2T(r, addr) \
    asm volatile("ldmatrix.sync.aligned.m8n8.x2.trans.shared.b16 {%0,%1}, [%2];" \
        : "=r"((r)[0]),"=r"((r)[1]) : "r"(addr))

__device__ __forceinline__ void mma16816(float* d, const uint32_t* a, const uint32_t* b){
    asm volatile("mma.sync.aligned.m16n8k16.row.col.f32.bf16.bf16.f32 "
        "{%0,%1,%2,%3}, {%4,%5,%6,%7}, {%8,%9}, {%0,%1,%2,%3};"
        : "+f"(d[0]), "+f"(d[1]), "+f"(d[2]), "+f"(d[3])
        : "r"(a[0]), "r"(a[1]), "r"(a[2]), "r"(a[3]), "r"(b[0]), "r"(b[1]));
}

// convMMA4 smem (bytes)
#define SB4   56160
#define SMEM4 (56160 + 22528)

// ---------------------------------------------------------------------------
__global__ void k_prepB(const float* __restrict__ cw, const float* __restrict__ offw)
{
    int i = blockIdx.x*256 + threadIdx.x;
    if (i >= 576*88) return;
    int k = i / 88, n = i - k*88;
    int tap = k >> 6, cin = k & 63;
    float v = 0.f;
    if (n < 64)      v = cw [(n*CC + cin)*9 + tap];
    else if (n < 82) v = offw[((n - 64)*CC + cin)*9 + tap];
    g_Bimg[i] = __float2bfloat16(v);
}

// ---------------------------------------------------------------------------
// T: transpose x NCHW f32 -> NHWC bf16 (g_xtb). grid 2048 = (b,h,chalf).
// ---------------------------------------------------------------------------
__global__ __launch_bounds__(256) void k_transpose(const float* __restrict__ x)
{
    __shared__ float s[32][129];
    int t = threadIdx.x;
    int b = blockIdx.x >> 8, h = (blockIdx.x >> 1) & 127, ch = blockIdx.x & 1;
    const float* xb = x + (b*CC + ch*32)*HWSZ + h*WW;
    for (int i = t; i < 32*32; i += 256) {
        int c = i >> 5, wq = i & 31;
        float4 v = *(const float4*)(xb + c*HWSZ + wq*4);
        s[c][wq*4 + 0] = v.x; s[c][wq*4 + 1] = v.y;
        s[c][wq*4 + 2] = v.z; s[c][wq*4 + 3] = v.w;
    }
    __syncthreads();
    __nv_bfloat16* ob = g_xtb + (size_t)(b*HH + h)*WW*CC + ch*32;
    for (int i = t; i < 128*16; i += 256) {
        int w = i >> 4, cp = i & 15;
        uint32_t p;
        asm("cvt.rn.satfinite.bf16x2.f32 %0, %1, %2;"
            : "=r"(p) : "f"(s[cp*2 + 1][w]), "f"(s[cp*2][w]));
        *(uint32_t*)(ob + w*CC + cp*2) = p;
    }
}

// ---------------------------------------------------------------------------
// convMMA4: per (b,h) row, M=128, N=88, K=576 bf16 HMMA (unchanged from R10).
// ---------------------------------------------------------------------------
__global__ __launch_bounds__(256, 2) void k_convMMA4(
    const float* __restrict__ offb, const float* __restrict__ pa_)
{
    extern __shared__ char smem[];
    uint32_t sb = smem_to_u32(smem);
    int t = threadIdx.x, wid = t >> 5, lane = t & 31;
    int b = blockIdx.x >> 7, h = blockIdx.x & 127;

    for (int i = t; i < 3*130*8; i += 256) {
        int rp = i >> 3, q = i & 7;
        int r = rp / 130, pxp = rp - r*130;
        int y = h + r - 1, xc = pxp - 1;
        uint4 v = make_uint4(0u, 0u, 0u, 0u);
        if (y >= 0 && y < HH && xc >= 0 && xc < WW)
            v = *(const uint4*)(g_xtb + ((size_t)(b*HH + y)*WW + xc)*CC + q*8);
        *(uint4*)(smem + rp*144 + q*16) = v;
    }
    {
        const uint4* s0 = (const uint4*)g_Bimg;
        uint4* d0 = (uint4*)(smem + SB4);
        for (int i = t; i < 704; i += 256) d0[i] = s0[i];
    }
    __syncthreads();

    float acc[11][4];
    #pragma unroll
    for (int nt = 0; nt < 11; nt++)
        #pragma unroll
        for (int j = 0; j < 4; j++) acc[nt][j] = 0.f;

    uint32_t l15  = lane & 15;
    uint32_t hi16 = (uint32_t)(lane >> 4) * 16;

    #pragma unroll 1
    for (int tap = 0; tap < 9; tap++) {
        int ky = tap / 3, kx = tap - ky*3;
        uint32_t bbase = sb + SB4 + (uint32_t)(tap & 1)*11264;
        if (tap < 8) {
            const uint4* srcB = (const uint4*)g_Bimg + (tap + 1)*704;
            uint4* dstB = (uint4*)(smem + SB4 + ((tap + 1) & 1)*11264);
            for (int i = t; i < 704; i += 256) dstB[i] = srcB[i];
        }
        uint32_t rowA = sb + (uint32_t)(ky*130 + kx + wid*16 + (int)l15)*144 + hi16;
        uint32_t rowB = bbase + l15*176;
        #pragma unroll
        for (int s = 0; s < 4; s++) {
            uint32_t a[4];
            LDSM_X4(a, rowA + s*32);
            uint32_t bA = rowB + (uint32_t)s*16*176;
            #pragma unroll
            for (int nt = 0; nt < 11; nt++) {
                uint32_t bf[2];
                LDSM_X2T(bf, bA + nt*16);
                mma16816(acc[nt], a, bf);
            }
        }
        __syncthreads();
    }

    float* sD = (float*)(smem);
    {
        int n0 = (lane & 3)*2;
        int px = wid*16 + (lane >> 2);
        #pragma unroll
        for (int nt = 0; nt < 11; nt++) {
            int n = nt*8 + n0;
            sD[n*132 + px]           = acc[nt][0];
            sD[(n + 1)*132 + px]     = acc[nt][1];
            sD[n*132 + px + 8]       = acc[nt][2];
            sD[(n + 1)*132 + px + 8] = acc[nt][3];
        }
    }
    __syncthreads();

    float pa = pa_[0];
    for (int oc = wid; oc < 82; oc += 8) {
        float v[4];
        #pragma unroll
        for (int j = 0; j < 4; j++) v[j] = sD[oc*132 + lane + 32*j];
        if (oc < 64) {
            float m = fmaxf(fmaxf(v[0], v[1]), fmaxf(v[2], v[3]));
            #pragma unroll
            for (int s = 16; s > 0; s >>= 1)
                m = fmaxf(m, __shfl_xor_sync(0xffffffffu, m, s));
            float e[4]; float sum = 0.f;
            #pragma unroll
            for (int j = 0; j < 4; j++) { e[j] = __expf(v[j] - m); sum += e[j]; }
            #pragma unroll
            for (int s = 16; s > 0; s >>= 1)
                sum += __shfl_xor_sync(0xffffffffu, sum, s);
            float inv = 1.0f / sum;
            int base = ((b*CC + oc)*HH + h)*WW + lane;
            #pragma unroll
            for (int j = 0; j < 4; j++) g_atten[base + 32*j] = e[j]*inv;
        } else {
            int o2 = oc - 64;
            float bo = offb[o2];
            int base = ((b*KOFF + o2)*HH + h)*WW + lane;
            #pragma unroll
            for (int j = 0; j < 4; j++) {
                float u = v[j] + bo;
                g_offset[base + 32*j] = u >= 0.f ? u : pa*u;
            }
        }
    }
}

// ---------------------------------------------------------------------------
// H: deformable grouped conv. Coeffs/indices precomputed once per block
//    (smem scoef), packed f32x2 weight-accumulate, bf16 gather.
//    grid 4096 = (b,h,quarter); block 256: t = pl*16 + gh.
// smem: scoef [9][32][8 words] 9216B; sw2 [16 gh][146 u64] 18688B;
//       sfeat [64][36] f32 9216B. Total 37120B.
// ---------------------------------------------------------------------------
#define SFS 36
#define SWROW 146   // u64 per gh row (144 used + 2 pad; 292 words = 4 mod 32)
__global__ __launch_bounds__(256, 2) void k_deformH(
    const float* __restrict__ x, const float* __restrict__ dw,
    const float* __restrict__ db, float* __restrict__ out)
{
    extern __shared__ char smH[];
    uint32_t* sco = (uint32_t*)smH;                        // 2304 words
    u64* sw2      = (u64*)(smH + 9216);                    // 16*146 u64
    float* sfeat  = (float*)(smH + 9216 + 16*SWROW*8);     // 64*SFS f32

    int t = threadIdx.x;
    int b  = blockIdx.x >> 9;
    int h  = (blockIdx.x >> 2) & 127;
    int q  = blockIdx.x & 3;
    int px0 = q*32;

    // ---- precompute coeffs + clamped indices for all (tap, px) ----
    for (int i = t; i < 288; i += 256) {
        int tap = i >> 5, pl = i & 31;
        int ky = tap / 3, kx = tap - ky*3;
        int w = px0 + pl;
        float dy = g_offset[(b*KOFF + 2*tap)*HWSZ + h*WW + w];
        float dx = g_offset[(b*KOFF + 2*tap + 1)*HWSZ + h*WW + w];
        float ys = (float)(h - 1 + ky) + dy;
        float xs = (float)(w - 1 + kx) + dx;
        float yf = floorf(ys), xf = floorf(xs);
        float ay = ys - yf, ax = xs - xf;
        int iy0 = (int)yf, ix0 = (int)xf;
        float my0 = (iy0 >= 0  && iy0 < HH)     ? 1.f : 0.f;
        float my1 = (iy0 >= -1 && iy0 + 1 < HH) ? 1.f : 0.f;
        float mx0 = (ix0 >= 0  && ix0 < WW)     ? 1.f : 0.f;
        float mx1 = (ix0 >= -1 && ix0 + 1 < WW) ? 1.f : 0.f;
        int cy0 = min(max(iy0, 0), HH - 1), cy1 = min(max(iy0 + 1, 0), HH - 1);
        int cx0 = min(max(ix0, 0), WW - 1), cx1 = min(max(ix0 + 1, 0), WW - 1);
        uint4 I = make_uint4((uint32_t)((cy0*WW + cx0)*CC),
                             (uint32_t)((cy0*WW + cx1)*CC),
                             (uint32_t)((cy1*WW + cx0)*CC),
                             (uint32_t)((cy1*WW + cx1)*CC));
        uint4 Cq = make_uint4(__float_as_uint((1.f - ay)*(1.f - ax)*my0*mx0),
                              __float_as_uint((1.f - ay)*ax*my0*mx1),
                              __float_as_uint(ay*(1.f - ax)*my1*mx0),
                              __float_as_uint(ay*ax*my1*mx1));
        *(uint4*)(sco + i*8)     = I;
        *(uint4*)(sco + i*8 + 4) = Cq;
    }
    // ---- stage packed weight pairs: sw2[gh*SWROW + k*16 + ci*4 + p] ----
    for (int i = t; i < 16*9*16; i += 256) {
        int gh = i / 144; int rem = i - gh*144;
        int tap = rem >> 4; int j = rem & 15;
        int ci = j >> 2, p = j & 3;
        int g = gh >> 1, half = gh & 1;
        int base = ((g*8 + 2*p)*8 + half*4 + ci)*9 + tap;
        sw2[gh*SWROW + tap*16 + ci*4 + p] = pk2(dw[base], dw[base + 8*9]);
    }
    __syncthreads();

    int pl = t >> 4, gh = t & 15;
    int g = gh >> 1, half = gh & 1;

    u64 acc0[4], acc1[4];
    #pragma unroll
    for (int p = 0; p < 4; p++) {
        u64 bo = half ? 0ULL : pk2(db[g*8 + 2*p], db[g*8 + 2*p + 1]);
        acc0[p] = bo; acc1[p] = bo;
    }

    const __nv_bfloat16* xgb = g_xtb + (size_t)b*HWSZ*CC + g*8 + half*4;

    #pragma unroll 1
    for (int k = 0; k < 9; k++) {
        // tap weights -> registers (16 u64 via 8 LDS.128)
        u64 W2[16];
        {
            const uint4* wt4 = (const uint4*)(sw2 + gh*SWROW + k*16);
            uint4 tmp[8];
            #pragma unroll
            for (int j = 0; j < 8; j++) tmp[j] = wt4[j];
            #pragma unroll
            for (int j = 0; j < 16; j++) W2[j] = ((u64*)tmp)[j];
        }
        #pragma unroll
        for (int p2 = 0; p2 < 2; p2++) {
            int plo = pl + p2*16;
            u64* acc = p2 ? acc1 : acc0;
            uint4 I  = *(const uint4*)(sco + (k*32 + plo)*8);
            uint4 Cq = *(const uint4*)(sco + (k*32 + plo)*8 + 4);
            float c00 = __uint_as_float(Cq.x), c01 = __uint_as_float(Cq.y);
            float c10 = __uint_as_float(Cq.z), c11 = __uint_as_float(Cq.w);
            uint2 A  = *(const uint2*)(xgb + I.x);
            uint2 Bv = *(const uint2*)(xgb + I.y);
            uint2 Cv = *(const uint2*)(xgb + I.z);
            uint2 D  = *(const uint2*)(xgb + I.w);
            float s0 = c00*bfLO(A.x) + c01*bfLO(Bv.x) + c10*bfLO(Cv.x) + c11*bfLO(D.x);
            float s1 = c00*bfHI(A.x) + c01*bfHI(Bv.x) + c10*bfHI(Cv.x) + c11*bfHI(D.x);
            float s2 = c00*bfLO(A.y) + c01*bfLO(Bv.y) + c10*bfLO(Cv.y) + c11*bfLO(D.y);
            float s3 = c00*bfHI(A.y) + c01*bfHI(Bv.y) + c10*bfHI(Cv.y) + c11*bfHI(D.y);
            u64 sp;
            sp = pk2(s0, s0);
            acc[0] = fma2(W2[0],  sp, acc[0]); acc[1] = fma2(W2[1],  sp, acc[1]);
            acc[2] = fma2(W2[2],  sp, acc[2]); acc[3] = fma2(W2[3],  sp, acc[3]);
            sp = pk2(s1, s1);
            acc[0] = fma2(W2[4],  sp, acc[0]); acc[1] = fma2(W2[5],  sp, acc[1]);
            acc[2] = fma2(W2[6],  sp, acc[2]); acc[3] = fma2(W2[7],  sp, acc[3]);
            sp = pk2(s2, s2);
            acc[0] = fma2(W2[8],  sp, acc[0]); acc[1] = fma2(W2[9],  sp, acc[1]);
            acc[2] = fma2(W2[10], sp, acc[2]); acc[3] = fma2(W2[11], sp, acc[3]);
            sp = pk2(s3, s3);
            acc[0] = fma2(W2[12], sp, acc[0]); acc[1] = fma2(W2[13], sp, acc[1]);
            acc[2] = fma2(W2[14], sp, acc[2]); acc[3] = fma2(W2[15], sp, acc[3]);
        }
    }

    // combine halves (lane^1) and stage
    #pragma unroll
    for (int p = 0; p < 4; p++) {
        float2 a0 = uf2(acc0[p]), a1 = uf2(acc1[p]);
        a0.x += __shfl_xor_sync(0xffffffffu, a0.x, 1);
        a0.y += __shfl_xor_sync(0xffffffffu, a0.y, 1);
        a1.x += __shfl_xor_sync(0xffffffffu, a1.x, 1);
        a1.y += __shfl_xor_sync(0xffffffffu, a1.y, 1);
        if (half == 0) {
            sfeat[(g*8 + 2*p)*SFS + pl]          = a0.x;
            sfeat[(g*8 + 2*p + 1)*SFS + pl]      = a0.y;
            sfeat[(g*8 + 2*p)*SFS + pl + 16]     = a1.x;
            sfeat[(g*8 + 2*p + 1)*SFS + pl + 16] = a1.y;
        }
    }
    __syncthreads();

    #pragma unroll
    for (int it = 0; it < 2; it++) {
        int idx = t + it*256;
        int oc = idx >> 3, p4 = idx & 7;
        float4 f = *(const float4*)(sfeat + oc*SFS + p4*4);
        int base = ((b*CC + oc)*HH + h)*WW + px0 + p4*4;
        float4 at = *(const float4*)(g_atten + base);
        float4 xv = *(const float4*)(x + base);
        float4 ov = make_float4(fmaf(at.x, f.x, xv.x), fmaf(at.y, f.y, xv.y),
                                fmaf(at.z, f.z, xv.z), fmaf(at.w, f.w, xv.w));
        *(float4*)(out + base) = ov;
    }
}

extern "C" void kernel_launch(void* const* d_in, const int* in_sizes, int n_in,
                              void* d_out, int out_size)
{
    const float* x    = (const float*)d_in[0];
    const float* offw = (const float*)d_in[1];
    const float* offb = (const float*)d_in[2];
    const float* pa   = (const float*)d_in[3];
    const float* dw   = (const float*)d_in[4];
    const float* db   = (const float*)d_in[5];
    const float* cw   = (const float*)d_in[6];
    float* out = (float*)d_out;

    const int smemH = 9216 + 16*SWROW*8 + 64*SFS*4;

    cudaFuncSetAttribute(k_convMMA4, cudaFuncAttributeMaxDynamicSharedMemorySize, SMEM4);
    cudaFuncSetAttribute(k_deformH,  cudaFuncAttributeMaxDynamicSharedMemorySize, smemH);

    k_prepB<<<198, 256>>>(cw, offw);
    k_transpose<<<2048, 256>>>(x);
    k_convMMA4<<<1024, 256, SMEM4>>>(offb, pa);
    k_deformH<<<4096, 256, smemH>>>(x, dw, db, out);
}

// round 12
// speedup vs baseline: 2.4792x; 1.0050x over previous
#include <cuda_runtime.h>
#include <cuda_bf16.h>
#include <cstdint>

#define BB 8
#define CC 64
#define HH 128
#define WW 128
#define HWSZ (HH*WW)
#define KOFF 18

// ---- scratch (no allocations allowed) ----
__device__ float g_offset[BB*KOFF*HWSZ];   // post-PReLU offsets [B,18,H,W]
__device__ float g_atten [BB*CC*HWSZ];     // softmax(conv) [B,64,H,W]
__device__ __align__(16) __nv_bfloat16 g_xtb[BB*HWSZ*CC];  // x NHWC bf16
__device__ __align__(16) __nv_bfloat16 g_Bimg[576*88];     // B weights [k=576][n=88] bf16

typedef unsigned long long u64;

__device__ __forceinline__ uint32_t smem_to_u32(const void* p){
    uint32_t a;
    asm("{ .reg .u64 t; cvta.to.shared.u64 t, %1; cvt.u32.u64 %0, t; }" : "=r"(a) : "l"(p));
    return a;
}
__device__ __forceinline__ float bfLO(uint32_t u){ return __uint_as_float(u << 16); }
__device__ __forceinline__ float bfHI(uint32_t u){ return __uint_as_float(u & 0xffff0000u); }
__device__ __forceinline__ u64 pk2(float lo, float hi){
    u64 r; asm("mov.b64 %0, {%1,%2};" : "=l"(r) : "f"(lo), "f"(hi)); return r;
}
__device__ __forceinline__ float2 uf2(u64 v){
    float2 f; asm("mov.b64 {%0,%1}, %2;" : "=f"(f.x), "=f"(f.y) : "l"(v)); return f;
}
__device__ __forceinline__ u64 fma2(u64 a, u64 b, u64 c){
    u64 d; asm("fma.rn.f32x2 %0, %1, %2, %3;" : "=l"(d) : "l"(a), "l"(b), "l"(c)); return d;
}

#define LDSM_X4(r, addr) \
    asm volatile("ldmatrix.sync.aligned.m8n8.x4.shared.b16 {%0,%1,%2,%3}, [%4];" \
        : "=r"((r)[0]),"=r"((r)[1]),"=r"((r)[2]),"=r"((r)[3]) : "r"(addr))
#define LDSM_X2T(r, addr) \
    asm volatile("ldmatrix.sync.aligned.m8n8.x2.trans.shared.b16 {%0,%1}, [%2];" \
        : "=r"((r)[0]),"=r"((r)[1]) : "r"(addr))

__device__ __forceinline__ void mma16816(float* d, const uint32_t* a, const uint32_t* b){
    asm volatile("mma.sync.aligned.m16n8k16.row.col.f32.bf16.bf16.f32 "
        "{%0,%1,%2,%3}, {%4,%5,%6,%7}, {%8,%9}, {%0,%1,%2,%3};"
        : "+f"(d[0]), "+f"(d[1]), "+f"(d[2]), "+f"(d[3])
        : "r"(a[0]), "r"(a[1]), "r"(a[2]), "r"(a[3]), "r"(b[0]), "r"(b[1]));
}

// convMMA4 smem (bytes)
#define SB4   56160
#define SMEM4 (56160 + 22528)

// ---------------------------------------------------------------------------
__global__ void k_prepB(const float* __restrict__ cw, const float* __restrict__ offw)
{
    int i = blockIdx.x*256 + threadIdx.x;
    if (i >= 576*88) return;
    int k = i / 88, n = i - k*88;
    int tap = k >> 6, cin = k & 63;
    float v = 0.f;
    if (n < 64)      v = cw [(n*CC + cin)*9 + tap];
    else if (n < 82) v = offw[((n - 64)*CC + cin)*9 + tap];
    g_Bimg[i] = __float2bfloat16(v);
}

// ---------------------------------------------------------------------------
// T: transpose x NCHW f32 -> NHWC bf16 (g_xtb). grid 2048 = (b,h,chalf).
// ---------------------------------------------------------------------------
__global__ __launch_bounds__(256) void k_transpose(const float* __restrict__ x)
{
    __shared__ float s[32][129];
    int t = threadIdx.x;
    int b = blockIdx.x >> 8, h = (blockIdx.x >> 1) & 127, ch = blockIdx.x & 1;
    const float* xb = x + (b*CC + ch*32)*HWSZ + h*WW;
    for (int i = t; i < 32*32; i += 256) {
        int c = i >> 5, wq = i & 31;
        float4 v = *(const float4*)(xb + c*HWSZ + wq*4);
        s[c][wq*4 + 0] = v.x; s[c][wq*4 + 1] = v.y;
        s[c][wq*4 + 2] = v.z; s[c][wq*4 + 3] = v.w;
    }
    __syncthreads();
    __nv_bfloat16* ob = g_xtb + (size_t)(b*HH + h)*WW*CC + ch*32;
    for (int i = t; i < 128*16; i += 256) {
        int w = i >> 4, cp = i & 15;
        uint32_t p;
        asm("cvt.rn.satfinite.bf16x2.f32 %0, %1, %2;"
            : "=r"(p) : "f"(s[cp*2 + 1][w]), "f"(s[cp*2][w]));
        *(uint32_t*)(ob + w*CC + cp*2) = p;
    }
}

// ---------------------------------------------------------------------------
// convMMA4: per (b,h) row, M=128, N=88, K=576 bf16 HMMA (unchanged from R10).
// ---------------------------------------------------------------------------
__global__ __launch_bounds__(256, 2) void k_convMMA4(
    const float* __restrict__ offb, const float* __restrict__ pa_)
{
    extern __shared__ char smem[];
    uint32_t sb = smem_to_u32(smem);
    int t = threadIdx.x, wid = t >> 5, lane = t & 31;
    int b = blockIdx.x >> 7, h = blockIdx.x & 127;

    for (int i = t; i < 3*130*8; i += 256) {
        int rp = i >> 3, q = i & 7;
        int r = rp / 130, pxp = rp - r*130;
        int y = h + r - 1, xc = pxp - 1;
        uint4 v = make_uint4(0u, 0u, 0u, 0u);
        if (y >= 0 && y < HH && xc >= 0 && xc < WW)
            v = *(const uint4*)(g_xtb + ((size_t)(b*HH + y)*WW + xc)*CC + q*8);
        *(uint4*)(smem + rp*144 + q*16) = v;
    }
    {
        const uint4* s0 = (const uint4*)g_Bimg;
        uint4* d0 = (uint4*)(smem + SB4);
        for (int i = t; i < 704; i += 256) d0[i] = s0[i];
    }
    __syncthreads();

    float acc[11][4];
    #pragma unroll
    for (int nt = 0; nt < 11; nt++)
        #pragma unroll
        for (int j = 0; j < 4; j++) acc[nt][j] = 0.f;

    uint32_t l15  = lane & 15;
    uint32_t hi16 = (uint32_t)(lane >> 4) * 16;

    #pragma unroll 1
    for (int tap = 0; tap < 9; tap++) {
        int ky = tap / 3, kx = tap - ky*3;
        uint32_t bbase = sb + SB4 + (uint32_t)(tap & 1)*11264;
        if (tap < 8) {
            const uint4* srcB = (const uint4*)g_Bimg + (tap + 1)*704;
            uint4* dstB = (uint4*)(smem + SB4 + ((tap + 1) & 1)*11264);
            for (int i = t; i < 704; i += 256) dstB[i] = srcB[i];
        }
        uint32_t rowA = sb + (uint32_t)(ky*130 + kx + wid*16 + (int)l15)*144 + hi16;
        uint32_t rowB = bbase + l15*176;
        #pragma unroll
        for (int s = 0; s < 4; s++) {
            uint32_t a[4];
            LDSM_X4(a, rowA + s*32);
            uint32_t bA = rowB + (uint32_t)s*16*176;
            #pragma unroll
            for (int nt = 0; nt < 11; nt++) {
                uint32_t bf[2];
                LDSM_X2T(bf, bA + nt*16);
                mma16816(acc[nt], a, bf);
            }
        }
        __syncthreads();
    }

    float* sD = (float*)(smem);
    {
        int n0 = (lane & 3)*2;
        int px = wid*16 + (lane >> 2);
        #pragma unroll
        for (int nt = 0; nt < 11; nt++) {
            int n = nt*8 + n0;
            sD[n*132 + px]           = acc[nt][0];
            sD[(n + 1)*132 + px]     = acc[nt][1];
            sD[n*132 + px + 8]       = acc[nt][2];
            sD[(n + 1)*132 + px + 8] = acc[nt][3];
        }
    }
    __syncthreads();

    float pa = pa_[0];
    for (int oc = wid; oc < 82; oc += 8) {
        float v[4];
        #pragma unroll
        for (int j = 0; j < 4; j++) v[j] = sD[oc*132 + lane + 32*j];
        if (oc < 64) {
            float m = fmaxf(fmaxf(v[0], v[1]), fmaxf(v[2], v[3]));
            #pragma unroll
            for (int s = 16; s > 0; s >>= 1)
                m = fmaxf(m, __shfl_xor_sync(0xffffffffu, m, s));
            float e[4]; float sum = 0.f;
            #pragma unroll
            for (int j = 0; j < 4; j++) { e[j] = __expf(v[j] - m); sum += e[j]; }
            #pragma unroll
            for (int s = 16; s > 0; s >>= 1)
                sum += __shfl_xor_sync(0xffffffffu, sum, s);
            float inv = 1.0f / sum;
            int base = ((b*CC + oc)*HH + h)*WW + lane;
            #pragma unroll
            for (int j = 0; j < 4; j++) g_atten[base + 32*j] = e[j]*inv;
        } else {
            int o2 = oc - 64;
            float bo = offb[o2];
            int base = ((b*KOFF + o2)*HH + h)*WW + lane;
            #pragma unroll
            for (int j = 0; j < 4; j++) {
                float u = v[j] + bo;
                g_offset[base + 32*j] = u >= 0.f ? u : pa*u;
            }
        }
    }
}

// ---------------------------------------------------------------------------
// I: deformable grouped conv. 4 px per thread (weights amortized 4x),
//    conflict-free weight banking (row stride 147 u64, LDS.64).
//    grid 2048 = (b,h,rowhalf); block 256: t = pl*16 + gh, covers 64 px.
// smem: sco [9][64][8 w] 18432B; sw2 16x147 u64 18816B; sfeat [64][68] 17408B.
// ---------------------------------------------------------------------------
#define SFS2 68
#define SWR 147   // u64 per gh row: 294 words = 6 mod 32 -> 16 distinct banks
__global__ __launch_bounds__(256, 2) void k_deformI(
    const float* __restrict__ x, const float* __restrict__ dw,
    const float* __restrict__ db, float* __restrict__ out)
{
    extern __shared__ char smH[];
    uint32_t* sco = (uint32_t*)smH;                        // 9*64*8 words
    u64* sw2      = (u64*)(smH + 18432);                   // 16*147 u64
    float* sfeat  = (float*)(smH + 18432 + 16*SWR*8);      // 64*SFS2

    int t = threadIdx.x;
    int b  = blockIdx.x >> 8;
    int h  = (blockIdx.x >> 1) & 127;
    int hb = blockIdx.x & 1;
    int px0 = hb*64;

    // ---- precompute coeffs + clamped byte-index offsets for all (tap, px) ----
    for (int i = t; i < 576; i += 256) {
        int tap = i >> 6, pl = i & 63;
        int ky = tap / 3, kx = tap - ky*3;
        int w = px0 + pl;
        float dy = g_offset[(b*KOFF + 2*tap)*HWSZ + h*WW + w];
        float dx = g_offset[(b*KOFF + 2*tap + 1)*HWSZ + h*WW + w];
        float ys = (float)(h - 1 + ky) + dy;
        float xs = (float)(w - 1 + kx) + dx;
        float yf = floorf(ys), xf = floorf(xs);
        float ay = ys - yf, ax = xs - xf;
        int iy0 = (int)yf, ix0 = (int)xf;
        float my0 = (iy0 >= 0  && iy0 < HH)     ? 1.f : 0.f;
        float my1 = (iy0 >= -1 && iy0 + 1 < HH) ? 1.f : 0.f;
        float mx0 = (ix0 >= 0  && ix0 < WW)     ? 1.f : 0.f;
        float mx1 = (ix0 >= -1 && ix0 + 1 < WW) ? 1.f : 0.f;
        int cy0 = min(max(iy0, 0), HH - 1), cy1 = min(max(iy0 + 1, 0), HH - 1);
        int cx0 = min(max(ix0, 0), WW - 1), cx1 = min(max(ix0 + 1, 0), WW - 1);
        uint4 I = make_uint4((uint32_t)((cy0*WW + cx0)*CC),
                             (uint32_t)((cy0*WW + cx1)*CC),
                             (uint32_t)((cy1*WW + cx0)*CC),
                             (uint32_t)((cy1*WW + cx1)*CC));
        uint4 Cq = make_uint4(__float_as_uint((1.f - ay)*(1.f - ax)*my0*mx0),
                              __float_as_uint((1.f - ay)*ax*my0*mx1),
                              __float_as_uint(ay*(1.f - ax)*my1*mx0),
                              __float_as_uint(ay*ax*my1*mx1));
        *(uint4*)(sco + i*8)     = I;
        *(uint4*)(sco + i*8 + 4) = Cq;
    }
    // ---- stage packed weight pairs: sw2[gh*SWR + tap*16 + ci*4 + p] ----
    for (int i = t; i < 16*9*16; i += 256) {
        int gh = i / 144; int rem = i - gh*144;
        int tap = rem >> 4; int j = rem & 15;
        int ci = j >> 2, p = j & 3;
        int g = gh >> 1, half = gh & 1;
        int base = ((g*8 + 2*p)*8 + half*4 + ci)*9 + tap;
        sw2[gh*SWR + tap*16 + ci*4 + p] = pk2(dw[base], dw[base + 72]);
    }
    __syncthreads();

    int pl = t >> 4, gh = t & 15;
    int g = gh >> 1, half = gh & 1;

    u64 acc[4][4];
    #pragma unroll
    for (int p = 0; p < 4; p++) {
        u64 bo = half ? 0ULL : pk2(db[g*8 + 2*p], db[g*8 + 2*p + 1]);
        #pragma unroll
        for (int p2 = 0; p2 < 4; p2++) acc[p2][p] = bo;
    }

    const __nv_bfloat16* xgb = g_xtb + (size_t)b*HWSZ*CC + g*8 + half*4;
    const u64* sw2g = sw2 + gh*SWR;

    #pragma unroll 1
    for (int k = 0; k < 9; k++) {
        u64 W2[16];
        {
            const u64* wt = sw2g + k*16;
            #pragma unroll
            for (int j = 0; j < 16; j++) W2[j] = wt[j];
        }
        #pragma unroll
        for (int p2 = 0; p2 < 4; p2++) {
            int plo = pl + p2*16;
            uint4 I  = *(const uint4*)(sco + (k*64 + plo)*8);
            uint4 Cq = *(const uint4*)(sco + (k*64 + plo)*8 + 4);
            float c00 = __uint_as_float(Cq.x), c01 = __uint_as_float(Cq.y);
            float c10 = __uint_as_float(Cq.z), c11 = __uint_as_float(Cq.w);
            uint2 A  = *(const uint2*)(xgb + I.x);
            uint2 Bv = *(const uint2*)(xgb + I.y);
            uint2 Cv = *(const uint2*)(xgb + I.z);
            uint2 D  = *(const uint2*)(xgb + I.w);
            float s0 = c00*bfLO(A.x) + c01*bfLO(Bv.x) + c10*bfLO(Cv.x) + c11*bfLO(D.x);
            float s1 = c00*bfHI(A.x) + c01*bfHI(Bv.x) + c10*bfHI(Cv.x) + c11*bfHI(D.x);
            float s2 = c00*bfLO(A.y) + c01*bfLO(Bv.y) + c10*bfLO(Cv.y) + c11*bfLO(D.y);
            float s3 = c00*bfHI(A.y) + c01*bfHI(Bv.y) + c10*bfHI(Cv.y) + c11*bfHI(D.y);
            u64* ac = acc[p2];
            u64 sp;
            sp = pk2(s0, s0);
            ac[0] = fma2(W2[0],  sp, ac[0]); ac[1] = fma2(W2[1],  sp, ac[1]);
            ac[2] = fma2(W2[2],  sp, ac[2]); ac[3] = fma2(W2[3],  sp, ac[3]);
            sp = pk2(s1, s1);
            ac[0] = fma2(W2[4],  sp, ac[0]); ac[1] = fma2(W2[5],  sp, ac[1]);
            ac[2] = fma2(W2[6],  sp, ac[2]); ac[3] = fma2(W2[7],  sp, ac[3]);
            sp = pk2(s2, s2);
            ac[0] = fma2(W2[8],  sp, ac[0]); ac[1] = fma2(W2[9],  sp, ac[1]);
            ac[2] = fma2(W2[10], sp, ac[2]); ac[3] = fma2(W2[11], sp, ac[3]);
            sp = pk2(s3, s3);
            ac[0] = fma2(W2[12], sp, ac[0]); ac[1] = fma2(W2[13], sp, ac[1]);
            ac[2] = fma2(W2[14], sp, ac[2]); ac[3] = fma2(W2[15], sp, ac[3]);
        }
    }

    // combine halves (lane^1 = same pl, other half) and stage
    #pragma unroll
    for (int p2 = 0; p2 < 4; p2++) {
        #pragma unroll
        for (int p = 0; p < 4; p++) {
            float2 a = uf2(acc[p2][p]);
            a.x += __shfl_xor_sync(0xffffffffu, a.x, 1);
            a.y += __shfl_xor_sync(0xffffffffu, a.y, 1);
            if (half == 0) {
                sfeat[(g*8 + 2*p)*SFS2 + pl + p2*16]     = a.x;
                sfeat[(g*8 + 2*p + 1)*SFS2 + pl + p2*16] = a.y;
            }
        }
    }
    __syncthreads();

    // coalesced epilogue: out = atten*feat + x (64 oc x 64 px, 4 float4/thread)
    #pragma unroll
    for (int it = 0; it < 4; it++) {
        int idx = t + it*256;
        int oc = idx >> 4, p4 = idx & 15;
        float4 f = *(const float4*)(sfeat + oc*SFS2 + p4*4);
        int base = ((b*CC + oc)*HH + h)*WW + px0 + p4*4;
        float4 at = *(const float4*)(g_atten + base);
        float4 xv = *(const float4*)(x + base);
        float4 ov = make_float4(fmaf(at.x, f.x, xv.x), fmaf(at.y, f.y, xv.y),
                                fmaf(at.z, f.z, xv.z), fmaf(at.w, f.w, xv.w));
        *(float4*)(out + base) = ov;
    }
}

extern "C" void kernel_launch(void* const* d_in, const int* in_sizes, int n_in,
                              void* d_out, int out_size)
{
    const float* x    = (const float*)d_in[0];
    const float* offw = (const float*)d_in[1];
    const float* offb = (const float*)d_in[2];
    const float* pa   = (const float*)d_in[3];
    const float* dw   = (const float*)d_in[4];
    const float* db   = (const float*)d_in[5];
    const float* cw   = (const float*)d_in[6];
    float* out = (float*)d_out;

    const int smemI = 18432 + 16*SWR*8 + 64*SFS2*4;   // 54656

    cudaFuncSetAttribute(k_convMMA4, cudaFuncAttributeMaxDynamicSharedMemorySize, SMEM4);
    cudaFuncSetAttribute(k_deformI,  cudaFuncAttributeMaxDynamicSharedMemorySize, smemI);

    k_prepB<<<198, 256>>>(cw, offw);
    k_transpose<<<2048, 256>>>(x);
    k_convMMA4<<<1024, 256, SMEM4>>>(offb, pa);
    k_deformI<<<2048, 256, smemI>>>(x, dw, db, out);
}

// round 13
// speedup vs baseline: 2.6719x; 1.0778x over previous
#include <cuda_runtime.h>
#include <cuda_bf16.h>
#include <cstdint>

#define BB 8
#define CC 64
#define HH 128
#define WW 128
#define HWSZ (HH*WW)
#define KOFF 18

// ---- scratch (no allocations allowed) ----
__device__ float g_offset[BB*KOFF*HWSZ];   // post-PReLU offsets [B,18,H,W]
__device__ float g_atten [BB*CC*HWSZ];     // softmax(conv) [B,64,H,W]
__device__ __align__(16) __nv_bfloat16 g_xtb[BB*HWSZ*CC];  // x NHWC bf16
__device__ __align__(16) __nv_bfloat16 g_Bimg[576*88];     // B weights [k=576][n=88] bf16
__device__ float g_dummy[1];

typedef unsigned long long u64;

__device__ __forceinline__ uint32_t smem_to_u32(const void* p){
    uint32_t a;
    asm("{ .reg .u64 t; cvta.to.shared.u64 t, %1; cvt.u32.u64 %0, t; }" : "=r"(a) : "l"(p));
    return a;
}
__device__ __forceinline__ float bfLO(uint32_t u){ return __uint_as_float(u << 16); }
__device__ __forceinline__ float bfHI(uint32_t u){ return __uint_as_float(u & 0xffff0000u); }
__device__ __forceinline__ u64 pk2(float lo, float hi){
    u64 r; asm("mov.b64 %0, {%1,%2};" : "=l"(r) : "f"(lo), "f"(hi)); return r;
}
__device__ __forceinline__ float2 uf2(u64 v){
    float2 f; asm("mov.b64 {%0,%1}, %2;" : "=f"(f.x), "=f"(f.y) : "l"(v)); return f;
}
__device__ __forceinline__ u64 fma2(u64 a, u64 b, u64 c){
    u64 d; asm("fma.rn.f32x2 %0, %1, %2, %3;" : "=l"(d) : "l"(a), "l"(b), "l"(c)); return d;
}

#define LDSM_X4(r, addr) \
    asm volatile("ldmatrix.sync.aligned.m8n8.x4.shared.b16 {%0,%1,%2,%3}, [%4];" \
        : "=r"((r)[0]),"=r"((r)[1]),"=r"((r)[2]),"=r"((r)[3]) : "r"(addr))
#define LDSM_X2T(r, addr) \
    asm volatile("ldmatrix.sync.aligned.m8n8.x2.trans.shared.b16 {%0,%1}, [%2];" \
        : "=r"((r)[0]),"=r"((r)[1]) : "r"(addr))

__device__ __forceinline__ void mma16816(float* d, const uint32_t* a, const uint32_t* b){
    asm volatile("mma.sync.aligned.m16n8k16.row.col.f32.bf16.bf16.f32 "
        "{%0,%1,%2,%3}, {%4,%5,%6,%7}, {%8,%9}, {%0,%1,%2,%3};"
        : "+f"(d[0]), "+f"(d[1]), "+f"(d[2]), "+f"(d[3])
        : "r"(a[0]), "r"(a[1]), "r"(a[2]), "r"(a[3]), "r"(b[0]), "r"(b[1]));
}

// convMMA5 smem (bytes): sx 4 rows x 130 px x 144B = 74880; B dbuf 2x11264.
// sD (88 x 264 f32 = 92928B) aliases [0,...) after mainloop.
#define SB5   74880
#define SMEM5 (74880 + 22528)

// ---------------------------------------------------------------------------
__global__ void k_prepB(const float* __restrict__ cw, const float* __restrict__ offw)
{
    int i = blockIdx.x*256 + threadIdx.x;
    if (i >= 576*88) return;
    int k = i / 88, n = i - k*88;
    int tap = k >> 6, cin = k & 63;
    float v = 0.f;
    if (n < 64)      v = cw [(n*CC + cin)*9 + tap];
    else if (n < 82) v = offw[((n - 64)*CC + cin)*9 + tap];
    g_Bimg[i] = __float2bfloat16(v);
}

__global__ void k_dummy() { if (threadIdx.x == 0) g_dummy[0] = 0.f; }

// ---------------------------------------------------------------------------
// T: transpose x NCHW f32 -> NHWC bf16 (g_xtb). grid 2048 = (b,h,chalf).
// ---------------------------------------------------------------------------
__global__ __launch_bounds__(256) void k_transpose(const float* __restrict__ x)
{
    __shared__ float s[32][129];
    int t = threadIdx.x;
    int b = blockIdx.x >> 8, h = (blockIdx.x >> 1) & 127, ch = blockIdx.x & 1;
    const float* xb = x + (b*CC + ch*32)*HWSZ + h*WW;
    for (int i = t; i < 32*32; i += 256) {
        int c = i >> 5, wq = i & 31;
        float4 v = *(const float4*)(xb + c*HWSZ + wq*4);
        s[c][wq*4 + 0] = v.x; s[c][wq*4 + 1] = v.y;
        s[c][wq*4 + 2] = v.z; s[c][wq*4 + 3] = v.w;
    }
    __syncthreads();
    __nv_bfloat16* ob = g_xtb + (size_t)(b*HH + h)*WW*CC + ch*32;
    for (int i = t; i < 128*16; i += 256) {
        int w = i >> 4, cp = i & 15;
        uint32_t p;
        asm("cvt.rn.satfinite.bf16x2.f32 %0, %1, %2;"
            : "=r"(p) : "f"(s[cp*2 + 1][w]), "f"(s[cp*2][w]));
        *(uint32_t*)(ob + w*CC + cp*2) = p;
    }
}

// ---------------------------------------------------------------------------
// convMMA5: M=256 (2 rows), N=88, K=576 bf16 HMMA. Warp = 32 px = 2 A-tiles
// sharing each B fragment (halves B-LDSM per MMA). B streamed (double buffer)
// so smem stays 97.4KB -> 2 blocks/SM. grid 512 = (b, h-pair).
// ---------------------------------------------------------------------------
__global__ __launch_bounds__(256, 2) void k_convMMA5(
    const float* __restrict__ offb, const float* __restrict__ pa_)
{
    extern __shared__ char smem[];
    uint32_t sb = smem_to_u32(smem);
    int t = threadIdx.x, wid = t >> 5, lane = t & 31;
    int b = blockIdx.x >> 6, hp = blockIdx.x & 63;
    int h0 = hp*2;

    // stage sx: rows h0-1..h0+2 (4 rows), 130 px, 64ch bf16, stride 144B
    for (int i = t; i < 4*130*8; i += 256) {
        int rp = i >> 3, q = i & 7;
        int r = rp / 130, pxp = rp - r*130;
        int y = h0 + r - 1, xc = pxp - 1;
        uint4 v = make_uint4(0u, 0u, 0u, 0u);
        if (y >= 0 && y < HH && xc >= 0 && xc < WW)
            v = *(const uint4*)(g_xtb + ((size_t)(b*HH + y)*WW + xc)*CC + q*8);
        *(uint4*)(smem + rp*144 + q*16) = v;
    }
    // preload B tap 0
    {
        const uint4* s0 = (const uint4*)g_Bimg;
        uint4* d0 = (uint4*)(smem + SB5);
        for (int i = t; i < 704; i += 256) d0[i] = s0[i];
    }
    __syncthreads();

    float acc[2][11][4];
    #pragma unroll
    for (int a = 0; a < 2; a++)
        #pragma unroll
        for (int nt = 0; nt < 11; nt++)
            #pragma unroll
            for (int j = 0; j < 4; j++) acc[a][nt][j] = 0.f;

    uint32_t l15  = lane & 15;
    uint32_t hi16 = (uint32_t)(lane >> 4) * 16;
    int orow = wid >> 2, pxq = (wid & 3)*32;

    #pragma unroll 1
    for (int tap = 0; tap < 9; tap++) {
        int ky = tap / 3, kx = tap - ky*3;
        uint32_t bbase = sb + SB5 + (uint32_t)(tap & 1)*11264;
        if (tap < 8) {
            const uint4* srcB = (const uint4*)g_Bimg + (tap + 1)*704;
            uint4* dstB = (uint4*)(smem + SB5 + ((tap + 1) & 1)*11264);
            for (int i = t; i < 704; i += 256) dstB[i] = srcB[i];
        }
        uint32_t rowA0 = sb + (uint32_t)((orow + ky)*130 + kx + pxq + (int)l15)*144 + hi16;
        uint32_t rowB  = bbase + l15*176;
        #pragma unroll
        for (int s = 0; s < 4; s++) {
            uint32_t a0[4], a1[4];
            LDSM_X4(a0, rowA0 + s*32);
            LDSM_X4(a1, rowA0 + 16*144 + s*32);
            uint32_t bA = rowB + (uint32_t)s*16*176;
            #pragma unroll
            for (int nt = 0; nt < 11; nt++) {
                uint32_t bf[2];
                LDSM_X2T(bf, bA + nt*16);
                mma16816(acc[0][nt], a0, bf);
                mma16816(acc[1][nt], a1, bf);
            }
        }
        __syncthreads();
    }

    // fragments -> sD[oc][m] (m = orow*128 + px); aliases sx+B (dead now)
    float* sD = (float*)(smem);
    {
        int n0 = (lane & 3)*2;
        int m0 = orow*128 + pxq + (lane >> 2);
        #pragma unroll
        for (int a = 0; a < 2; a++) {
            int m = m0 + a*16;
            #pragma unroll
            for (int nt = 0; nt < 11; nt++) {
                int n = nt*8 + n0;
                sD[n*264 + m]           = acc[a][nt][0];
                sD[(n + 1)*264 + m]     = acc[a][nt][1];
                sD[n*264 + m + 8]       = acc[a][nt][2];
                sD[(n + 1)*264 + m + 8] = acc[a][nt][3];
            }
        }
    }
    __syncthreads();

    // epilogue: 164 tasks = 82 oc x 2 rows
    float pa = pa_[0];
    for (int idx = wid; idx < 164; idx += 8) {
        int oc = idx >> 1, row = idx & 1;
        int h = h0 + row;
        float v[4];
        #pragma unroll
        for (int j = 0; j < 4; j++) v[j] = sD[oc*264 + row*128 + lane + 32*j];
        if (oc < 64) {
            float m = fmaxf(fmaxf(v[0], v[1]), fmaxf(v[2], v[3]));
            #pragma unroll
            for (int s = 16; s > 0; s >>= 1)
                m = fmaxf(m, __shfl_xor_sync(0xffffffffu, m, s));
            float e[4]; float sum = 0.f;
            #pragma unroll
            for (int j = 0; j < 4; j++) { e[j] = __expf(v[j] - m); sum += e[j]; }
            #pragma unroll
            for (int s = 16; s > 0; s >>= 1)
                sum += __shfl_xor_sync(0xffffffffu, sum, s);
            float inv = 1.0f / sum;
            int base = ((b*CC + oc)*HH + h)*WW + lane;
            #pragma unroll
            for (int j = 0; j < 4; j++) g_atten[base + 32*j] = e[j]*inv;
        } else {
            int o2 = oc - 64;
            float bo = offb[o2];
            int base = ((b*KOFF + o2)*HH + h)*WW + lane;
            #pragma unroll
            for (int j = 0; j < 4; j++) {
                float u = v[j] + bo;
                g_offset[base + 32*j] = u >= 0.f ? u : pa*u;
            }
        }
    }
}

// ---------------------------------------------------------------------------
// I: deformable grouped conv (unchanged from R12).
// ---------------------------------------------------------------------------
#define SFS2 68
#define SWR 147
__global__ __launch_bounds__(256, 2) void k_deformI(
    const float* __restrict__ x, const float* __restrict__ dw,
    const float* __restrict__ db, float* __restrict__ out)
{
    extern __shared__ char smH[];
    uint32_t* sco = (uint32_t*)smH;
    u64* sw2      = (u64*)(smH + 18432);
    float* sfeat  = (float*)(smH + 18432 + 16*SWR*8);

    int t = threadIdx.x;
    int b  = blockIdx.x >> 8;
    int h  = (blockIdx.x >> 1) & 127;
    int hb = blockIdx.x & 1;
    int px0 = hb*64;

    for (int i = t; i < 576; i += 256) {
        int tap = i >> 6, pl = i & 63;
        int ky = tap / 3, kx = tap - ky*3;
        int w = px0 + pl;
        float dy = g_offset[(b*KOFF + 2*tap)*HWSZ + h*WW + w];
        float dx = g_offset[(b*KOFF + 2*tap + 1)*HWSZ + h*WW + w];
        float ys = (float)(h - 1 + ky) + dy;
        float xs = (float)(w - 1 + kx) + dx;
        float yf = floorf(ys), xf = floorf(xs);
        float ay = ys - yf, ax = xs - xf;
        int iy0 = (int)yf, ix0 = (int)xf;
        float my0 = (iy0 >= 0  && iy0 < HH)     ? 1.f : 0.f;
        float my1 = (iy0 >= -1 && iy0 + 1 < HH) ? 1.f : 0.f;
        float mx0 = (ix0 >= 0  && ix0 < WW)     ? 1.f : 0.f;
        float mx1 = (ix0 >= -1 && ix0 + 1 < WW) ? 1.f : 0.f;
        int cy0 = min(max(iy0, 0), HH - 1), cy1 = min(max(iy0 + 1, 0), HH - 1);
        int cx0 = min(max(ix0, 0), WW - 1), cx1 = min(max(ix0 + 1, 0), WW - 1);
        uint4 I = make_uint4((uint32_t)((cy0*WW + cx0)*CC),
                             (uint32_t)((cy0*WW + cx1)*CC),
                             (uint32_t)((cy1*WW + cx0)*CC),
                             (uint32_t)((cy1*WW + cx1)*CC));
        uint4 Cq = make_uint4(__float_as_uint((1.f - ay)*(1.f - ax)*my0*mx0),
                              __float_as_uint((1.f - ay)*ax*my0*mx1),
                              __float_as_uint(ay*(1.f - ax)*my1*mx0),
                              __float_as_uint(ay*ax*my1*mx1));
        *(uint4*)(sco + i*8)     = I;
        *(uint4*)(sco + i*8 + 4) = Cq;
    }
    for (int i = t; i < 16*9*16; i += 256) {
        int gh = i / 144; int rem = i - gh*144;
        int tap = rem >> 4; int j = rem & 15;
        int ci = j >> 2, p = j & 3;
        int g = gh >> 1, half = gh & 1;
        int base = ((g*8 + 2*p)*8 + half*4 + ci)*9 + tap;
        sw2[gh*SWR + tap*16 + ci*4 + p] = pk2(dw[base], dw[base + 72]);
    }
    __syncthreads();

    int pl = t >> 4, gh = t & 15;
    int g = gh >> 1, half = gh & 1;

    u64 acc[4][4];
    #pragma unroll
    for (int p = 0; p < 4; p++) {
        u64 bo = half ? 0ULL : pk2(db[g*8 + 2*p], db[g*8 + 2*p + 1]);
        #pragma unroll
        for (int p2 = 0; p2 < 4; p2++) acc[p2][p] = bo;
    }

    const __nv_bfloat16* xgb = g_xtb + (size_t)b*HWSZ*CC + g*8 + half*4;
    const u64* sw2g = sw2 + gh*SWR;

    #pragma unroll 1
    for (int k = 0; k < 9; k++) {
        u64 W2[16];
        {
            const u64* wt = sw2g + k*16;
            #pragma unroll
            for (int j = 0; j < 16; j++) W2[j] = wt[j];
        }
        #pragma unroll
        for (int p2 = 0; p2 < 4; p2++) {
            int plo = pl + p2*16;
            uint4 I  = *(const uint4*)(sco + (k*64 + plo)*8);
            uint4 Cq = *(const uint4*)(sco + (k*64 + plo)*8 + 4);
            float c00 = __uint_as_float(Cq.x), c01 = __uint_as_float(Cq.y);
            float c10 = __uint_as_float(Cq.z), c11 = __uint_as_float(Cq.w);
            uint2 A  = *(const uint2*)(xgb + I.x);
            uint2 Bv = *(const uint2*)(xgb + I.y);
            uint2 Cv = *(const uint2*)(xgb + I.z);
            uint2 D  = *(const uint2*)(xgb + I.w);
            float s0 = c00*bfLO(A.x) + c01*bfLO(Bv.x) + c10*bfLO(Cv.x) + c11*bfLO(D.x);
            float s1 = c00*bfHI(A.x) + c01*bfHI(Bv.x) + c10*bfHI(Cv.x) + c11*bfHI(D.x);
            float s2 = c00*bfLO(A.y) + c01*bfLO(Bv.y) + c10*bfLO(Cv.y) + c11*bfLO(D.y);
            float s3 = c00*bfHI(A.y) + c01*bfHI(Bv.y) + c10*bfHI(Cv.y) + c11*bfHI(D.y);
            u64* ac = acc[p2];
            u64 sp;
            sp = pk2(s0, s0);
            ac[0] = fma2(W2[0],  sp, ac[0]); ac[1] = fma2(W2[1],  sp, ac[1]);
            ac[2] = fma2(W2[2],  sp, ac[2]); ac[3] = fma2(W2[3],  sp, ac[3]);
            sp = pk2(s1, s1);
            ac[0] = fma2(W2[4],  sp, ac[0]); ac[1] = fma2(W2[5],  sp, ac[1]);
            ac[2] = fma2(W2[6],  sp, ac[2]); ac[3] = fma2(W2[7],  sp, ac[3]);
            sp = pk2(s2, s2);
            ac[0] = fma2(W2[8],  sp, ac[0]); ac[1] = fma2(W2[9],  sp, ac[1]);
            ac[2] = fma2(W2[10], sp, ac[2]); ac[3] = fma2(W2[11], sp, ac[3]);
            sp = pk2(s3, s3);
            ac[0] = fma2(W2[12], sp, ac[0]); ac[1] = fma2(W2[13], sp, ac[1]);
            ac[2] = fma2(W2[14], sp, ac[2]); ac[3] = fma2(W2[15], sp, ac[3]);
        }
    }

    #pragma unroll
    for (int p2 = 0; p2 < 4; p2++) {
        #pragma unroll
        for (int p = 0; p < 4; p++) {
            float2 a = uf2(acc[p2][p]);
            a.x += __shfl_xor_sync(0xffffffffu, a.x, 1);
            a.y += __shfl_xor_sync(0xffffffffu, a.y, 1);
            if (half == 0) {
                sfeat[(g*8 + 2*p)*SFS2 + pl + p2*16]     = a.x;
                sfeat[(g*8 + 2*p + 1)*SFS2 + pl + p2*16] = a.y;
            }
        }
    }
    __syncthreads();

    #pragma unroll
    for (int it = 0; it < 4; it++) {
        int idx = t + it*256;
        int oc = idx >> 4, p4 = idx & 15;
        float4 f = *(const float4*)(sfeat + oc*SFS2 + p4*4);
        int base = ((b*CC + oc)*HH + h)*WW + px0 + p4*4;
        float4 at = *(const float4*)(g_atten + base);
        float4 xv = *(const float4*)(x + base);
        float4 ov = make_float4(fmaf(at.x, f.x, xv.x), fmaf(at.y, f.y, xv.y),
                                fmaf(at.z, f.z, xv.z), fmaf(at.w, f.w, xv.w));
        *(float4*)(out + base) = ov;
    }
}

extern "C" void kernel_launch(void* const* d_in, const int* in_sizes, int n_in,
                              void* d_out, int out_size)
{
    const float* x    = (const float*)d_in[0];
    const float* offw = (const float*)d_in[1];
    const float* offb = (const float*)d_in[2];
    const float* pa   = (const float*)d_in[3];
    const float* dw   = (const float*)d_in[4];
    const float* db   = (const float*)d_in[5];
    const float* cw   = (const float*)d_in[6];
    float* out = (float*)d_out;

    const int smemI = 18432 + 16*SWR*8 + 64*SFS2*4;   // 54656

    cudaFuncSetAttribute(k_convMMA5, cudaFuncAttributeMaxDynamicSharedMemorySize, SMEM5);
    cudaFuncSetAttribute(k_deformI,  cudaFuncAttributeMaxDynamicSharedMemorySize, smemI);

    k_prepB<<<198, 256>>>(cw, offw);
    k_dummy<<<1, 32>>>();
    k_transpose<<<2048, 256>>>(x);
    k_convMMA5<<<512, 256, SMEM5>>>(offb, pa);     // launch #5 -> ncu capture
    k_deformI<<<2048, 256, smemI>>>(x, dw, db, out);
}

// round 14
// speedup vs baseline: 2.7338x; 1.0231x over previous
#include <cuda_runtime.h>
#include <cuda_bf16.h>
#include <cstdint>

#define BB 8
#define CC 64
#define HH 128
#define WW 128
#define HWSZ (HH*WW)
#define KOFF 18

// ---- scratch (no allocations allowed) ----
__device__ float g_offset[BB*KOFF*HWSZ];   // post-PReLU offsets [B,18,H,W]
__device__ float g_atten [BB*CC*HWSZ];     // softmax(conv) [B,64,H,W]
__device__ __align__(16) __nv_bfloat16 g_xtb[BB*HWSZ*CC];  // x NHWC bf16
__device__ __align__(16) __nv_bfloat16 g_Bimg[576*88];     // B weights [k=576][n=88] bf16

typedef unsigned long long u64;

__device__ __forceinline__ uint32_t smem_to_u32(const void* p){
    uint32_t a;
    asm("{ .reg .u64 t; cvta.to.shared.u64 t, %1; cvt.u32.u64 %0, t; }" : "=r"(a) : "l"(p));
    return a;
}
__device__ __forceinline__ float bfLO(uint32_t u){ return __uint_as_float(u << 16); }
__device__ __forceinline__ float bfHI(uint32_t u){ return __uint_as_float(u & 0xffff0000u); }
__device__ __forceinline__ u64 pk2(float lo, float hi){
    u64 r; asm("mov.b64 %0, {%1,%2};" : "=l"(r) : "f"(lo), "f"(hi)); return r;
}
__device__ __forceinline__ float2 uf2(u64 v){
    float2 f; asm("mov.b64 {%0,%1}, %2;" : "=f"(f.x), "=f"(f.y) : "l"(v)); return f;
}
__device__ __forceinline__ u64 fma2(u64 a, u64 b, u64 c){
    u64 d; asm("fma.rn.f32x2 %0, %1, %2, %3;" : "=l"(d) : "l"(a), "l"(b), "l"(c)); return d;
}

#define LDSM_X4(r, addr) \
    asm volatile("ldmatrix.sync.aligned.m8n8.x4.shared.b16 {%0,%1,%2,%3}, [%4];" \
        : "=r"((r)[0]),"=r"((r)[1]),"=r"((r)[2]),"=r"((r)[3]) : "r"(addr))
#define LDSM_X2T(r, addr) \
    asm volatile("ldmatrix.sync.aligned.m8n8.x2.trans.shared.b16 {%0,%1}, [%2];" \
        : "=r"((r)[0]),"=r"((r)[1]) : "r"(addr))

__device__ __forceinline__ void mma16816(float* d, const uint32_t* a, const uint32_t* b){
    asm volatile("mma.sync.aligned.m16n8k16.row.col.f32.bf16.bf16.f32 "
        "{%0,%1,%2,%3}, {%4,%5,%6,%7}, {%8,%9}, {%0,%1,%2,%3};"
        : "+f"(d[0]), "+f"(d[1]), "+f"(d[2]), "+f"(d[3])
        : "r"(a[0]), "r"(a[1]), "r"(a[2]), "r"(a[3]), "r"(b[0]), "r"(b[1]));
}

// convMMA5 smem (bytes)
#define SB5   74880
#define SMEM5 (74880 + 22528)

// ---------------------------------------------------------------------------
__global__ void k_prepB(const float* __restrict__ cw, const float* __restrict__ offw)
{
    int i = blockIdx.x*256 + threadIdx.x;
    if (i >= 576*88) return;
    int k = i / 88, n = i - k*88;
    int tap = k >> 6, cin = k & 63;
    float v = 0.f;
    if (n < 64)      v = cw [(n*CC + cin)*9 + tap];
    else if (n < 82) v = offw[((n - 64)*CC + cin)*9 + tap];
    g_Bimg[i] = __float2bfloat16(v);
}

// ---------------------------------------------------------------------------
// T: transpose x NCHW f32 -> NHWC bf16. grid 2048 = (b,h,chalf).
// ---------------------------------------------------------------------------
__global__ __launch_bounds__(256) void k_transpose(const float* __restrict__ x)
{
    __shared__ float s[32][129];
    int t = threadIdx.x;
    int b = blockIdx.x >> 8, h = (blockIdx.x >> 1) & 127, ch = blockIdx.x & 1;
    const float* xb = x + (b*CC + ch*32)*HWSZ + h*WW;
    for (int i = t; i < 32*32; i += 256) {
        int c = i >> 5, wq = i & 31;
        float4 v = *(const float4*)(xb + c*HWSZ + wq*4);
        s[c][wq*4 + 0] = v.x; s[c][wq*4 + 1] = v.y;
        s[c][wq*4 + 2] = v.z; s[c][wq*4 + 3] = v.w;
    }
    __syncthreads();
    __nv_bfloat16* ob = g_xtb + (size_t)(b*HH + h)*WW*CC + ch*32;
    for (int i = t; i < 128*16; i += 256) {
        int w = i >> 4, cp = i & 15;
        uint32_t p;
        asm("cvt.rn.satfinite.bf16x2.f32 %0, %1, %2;"
            : "=r"(p) : "f"(s[cp*2 + 1][w]), "f"(s[cp*2][w]));
        *(uint32_t*)(ob + w*CC + cp*2) = p;
    }
}

// ---------------------------------------------------------------------------
// convMMA5: M=256 (2 rows), N=88, K=576 bf16 HMMA (unchanged from R13).
// ---------------------------------------------------------------------------
__global__ __launch_bounds__(256, 2) void k_convMMA5(
    const float* __restrict__ offb, const float* __restrict__ pa_)
{
    extern __shared__ char smem[];
    uint32_t sb = smem_to_u32(smem);
    int t = threadIdx.x, wid = t >> 5, lane = t & 31;
    int b = blockIdx.x >> 6, hp = blockIdx.x & 63;
    int h0 = hp*2;

    for (int i = t; i < 4*130*8; i += 256) {
        int rp = i >> 3, q = i & 7;
        int r = rp / 130, pxp = rp - r*130;
        int y = h0 + r - 1, xc = pxp - 1;
        uint4 v = make_uint4(0u, 0u, 0u, 0u);
        if (y >= 0 && y < HH && xc >= 0 && xc < WW)
            v = *(const uint4*)(g_xtb + ((size_t)(b*HH + y)*WW + xc)*CC + q*8);
        *(uint4*)(smem + rp*144 + q*16) = v;
    }
    {
        const uint4* s0 = (const uint4*)g_Bimg;
        uint4* d0 = (uint4*)(smem + SB5);
        for (int i = t; i < 704; i += 256) d0[i] = s0[i];
    }
    __syncthreads();

    float acc[2][11][4];
    #pragma unroll
    for (int a = 0; a < 2; a++)
        #pragma unroll
        for (int nt = 0; nt < 11; nt++)
            #pragma unroll
            for (int j = 0; j < 4; j++) acc[a][nt][j] = 0.f;

    uint32_t l15  = lane & 15;
    uint32_t hi16 = (uint32_t)(lane >> 4) * 16;
    int orow = wid >> 2, pxq = (wid & 3)*32;

    #pragma unroll 1
    for (int tap = 0; tap < 9; tap++) {
        int ky = tap / 3, kx = tap - ky*3;
        uint32_t bbase = sb + SB5 + (uint32_t)(tap & 1)*11264;
        if (tap < 8) {
            const uint4* srcB = (const uint4*)g_Bimg + (tap + 1)*704;
            uint4* dstB = (uint4*)(smem + SB5 + ((tap + 1) & 1)*11264);
            for (int i = t; i < 704; i += 256) dstB[i] = srcB[i];
        }
        uint32_t rowA0 = sb + (uint32_t)((orow + ky)*130 + kx + pxq + (int)l15)*144 + hi16;
        uint32_t rowB  = bbase + l15*176;
        #pragma unroll
        for (int s = 0; s < 4; s++) {
            uint32_t a0[4], a1[4];
            LDSM_X4(a0, rowA0 + s*32);
            LDSM_X4(a1, rowA0 + 16*144 + s*32);
            uint32_t bA = rowB + (uint32_t)s*16*176;
            #pragma unroll
            for (int nt = 0; nt < 11; nt++) {
                uint32_t bf[2];
                LDSM_X2T(bf, bA + nt*16);
                mma16816(acc[0][nt], a0, bf);
                mma16816(acc[1][nt], a1, bf);
            }
        }
        __syncthreads();
    }

    float* sD = (float*)(smem);
    {
        int n0 = (lane & 3)*2;
        int m0 = orow*128 + pxq + (lane >> 2);
        #pragma unroll
        for (int a = 0; a < 2; a++) {
            int m = m0 + a*16;
            #pragma unroll
            for (int nt = 0; nt < 11; nt++) {
                int n = nt*8 + n0;
                sD[n*264 + m]           = acc[a][nt][0];
                sD[(n + 1)*264 + m]     = acc[a][nt][1];
                sD[n*264 + m + 8]       = acc[a][nt][2];
                sD[(n + 1)*264 + m + 8] = acc[a][nt][3];
            }
        }
    }
    __syncthreads();

    float pa = pa_[0];
    for (int idx = wid; idx < 164; idx += 8) {
        int oc = idx >> 1, row = idx & 1;
        int h = h0 + row;
        float v[4];
        #pragma unroll
        for (int j = 0; j < 4; j++) v[j] = sD[oc*264 + row*128 + lane + 32*j];
        if (oc < 64) {
            float m = fmaxf(fmaxf(v[0], v[1]), fmaxf(v[2], v[3]));
            #pragma unroll
            for (int s = 16; s > 0; s >>= 1)
                m = fmaxf(m, __shfl_xor_sync(0xffffffffu, m, s));
            float e[4]; float sum = 0.f;
            #pragma unroll
            for (int j = 0; j < 4; j++) { e[j] = __expf(v[j] - m); sum += e[j]; }
            #pragma unroll
            for (int s = 16; s > 0; s >>= 1)
                sum += __shfl_xor_sync(0xffffffffu, sum, s);
            float inv = 1.0f / sum;
            int base = ((b*CC + oc)*HH + h)*WW + lane;
            #pragma unroll
            for (int j = 0; j < 4; j++) g_atten[base + 32*j] = e[j]*inv;
        } else {
            int o2 = oc - 64;
            float bo = offb[o2];
            int base = ((b*KOFF + o2)*HH + h)*WW + lane;
            #pragma unroll
            for (int j = 0; j < 4; j++) {
                float u = v[j] + bo;
                g_offset[base + 32*j] = u >= 0.f ? u : pa*u;
            }
        }
    }
}

// ---------------------------------------------------------------------------
// H2: deformable grouped conv — 2 px/thread (low regs), conflict-free weight
//     banking (SWR=147 word-stride, LDS.64), 3 blocks/SM.
//     grid 4096 = (b,h,quarter); block 256: t = pl*16 + gh.
// smem: sco [9][32][8w] 9216B; sw2 16x147 u64 18816B; sfeat [64][36] 9216B.
// ---------------------------------------------------------------------------
#define SFS 36
#define SWR 147   // u64/row: 294 words = 6 mod 32 -> 16 gh rows on distinct banks
__global__ __launch_bounds__(256, 3) void k_deformH2(
    const float* __restrict__ x, const float* __restrict__ dw,
    const float* __restrict__ db, float* __restrict__ out)
{
    extern __shared__ char smH[];
    uint32_t* sco = (uint32_t*)smH;                        // 2304 words
    u64* sw2      = (u64*)(smH + 9216);                    // 16*147 u64
    float* sfeat  = (float*)(smH + 9216 + 16*SWR*8);       // 64*SFS f32

    int t = threadIdx.x;
    int b  = blockIdx.x >> 9;
    int h  = (blockIdx.x >> 2) & 127;
    int q  = blockIdx.x & 3;
    int px0 = q*32;

    // ---- precompute coeffs + clamped indices for all (tap, px) ----
    for (int i = t; i < 288; i += 256) {
        int tap = i >> 5, pl = i & 31;
        int ky = tap / 3, kx = tap - ky*3;
        int w = px0 + pl;
        float dy = g_offset[(b*KOFF + 2*tap)*HWSZ + h*WW + w];
        float dx = g_offset[(b*KOFF + 2*tap + 1)*HWSZ + h*WW + w];
        float ys = (float)(h - 1 + ky) + dy;
        float xs = (float)(w - 1 + kx) + dx;
        float yf = floorf(ys), xf = floorf(xs);
        float ay = ys - yf, ax = xs - xf;
        int iy0 = (int)yf, ix0 = (int)xf;
        float my0 = (iy0 >= 0  && iy0 < HH)     ? 1.f : 0.f;
        float my1 = (iy0 >= -1 && iy0 + 1 < HH) ? 1.f : 0.f;
        float mx0 = (ix0 >= 0  && ix0 < WW)     ? 1.f : 0.f;
        float mx1 = (ix0 >= -1 && ix0 + 1 < WW) ? 1.f : 0.f;
        int cy0 = min(max(iy0, 0), HH - 1), cy1 = min(max(iy0 + 1, 0), HH - 1);
        int cx0 = min(max(ix0, 0), WW - 1), cx1 = min(max(ix0 + 1, 0), WW - 1);
        uint4 I = make_uint4((uint32_t)((cy0*WW + cx0)*CC),
                             (uint32_t)((cy0*WW + cx1)*CC),
                             (uint32_t)((cy1*WW + cx0)*CC),
                             (uint32_t)((cy1*WW + cx1)*CC));
        uint4 Cq = make_uint4(__float_as_uint((1.f - ay)*(1.f - ax)*my0*mx0),
                              __float_as_uint((1.f - ay)*ax*my0*mx1),
                              __float_as_uint(ay*(1.f - ax)*my1*mx0),
                              __float_as_uint(ay*ax*my1*mx1));
        *(uint4*)(sco + i*8)     = I;
        *(uint4*)(sco + i*8 + 4) = Cq;
    }
    // ---- stage packed weight pairs ----
    for (int i = t; i < 16*9*16; i += 256) {
        int gh = i / 144; int rem = i - gh*144;
        int tap = rem >> 4; int j = rem & 15;
        int ci = j >> 2, p = j & 3;
        int g = gh >> 1, half = gh & 1;
        int base = ((g*8 + 2*p)*8 + half*4 + ci)*9 + tap;
        sw2[gh*SWR + tap*16 + ci*4 + p] = pk2(dw[base], dw[base + 72]);
    }
    __syncthreads();

    int pl = t >> 4, gh = t & 15;
    int g = gh >> 1, half = gh & 1;

    u64 acc0[4], acc1[4];
    #pragma unroll
    for (int p = 0; p < 4; p++) {
        u64 bo = half ? 0ULL : pk2(db[g*8 + 2*p], db[g*8 + 2*p + 1]);
        acc0[p] = bo; acc1[p] = bo;
    }

    const __nv_bfloat16* xgb = g_xtb + (size_t)b*HWSZ*CC + g*8 + half*4;
    const u64* sw2g = sw2 + gh*SWR;

    #pragma unroll 1
    for (int k = 0; k < 9; k++) {
        u64 W2[16];
        {
            const u64* wt = sw2g + k*16;
            #pragma unroll
            for (int j = 0; j < 16; j++) W2[j] = wt[j];
        }
        #pragma unroll
        for (int p2 = 0; p2 < 2; p2++) {
            int plo = pl + p2*16;
            u64* ac = p2 ? acc1 : acc0;
            uint4 I  = *(const uint4*)(sco + (k*32 + plo)*8);
            uint4 Cq = *(const uint4*)(sco + (k*32 + plo)*8 + 4);
            float c00 = __uint_as_float(Cq.x), c01 = __uint_as_float(Cq.y);
            float c10 = __uint_as_float(Cq.z), c11 = __uint_as_float(Cq.w);
            uint2 A  = *(const uint2*)(xgb + I.x);
            uint2 Bv = *(const uint2*)(xgb + I.y);
            uint2 Cv = *(const uint2*)(xgb + I.z);
            uint2 D  = *(const uint2*)(xgb + I.w);
            float s0 = c00*bfLO(A.x) + c01*bfLO(Bv.x) + c10*bfLO(Cv.x) + c11*bfLO(D.x);
            float s1 = c00*bfHI(A.x) + c01*bfHI(Bv.x) + c10*bfHI(Cv.x) + c11*bfHI(D.x);
            float s2 = c00*bfLO(A.y) + c01*bfLO(Bv.y) + c10*bfLO(Cv.y) + c11*bfLO(D.y);
            float s3 = c00*bfHI(A.y) + c01*bfHI(Bv.y) + c10*bfHI(Cv.y) + c11*bfHI(D.y);
            u64 sp;
            sp = pk2(s0, s0);
            ac[0] = fma2(W2[0],  sp, ac[0]); ac[1] = fma2(W2[1],  sp, ac[1]);
            ac[2] = fma2(W2[2],  sp, ac[2]); ac[3] = fma2(W2[3],  sp, ac[3]);
            sp = pk2(s1, s1);
            ac[0] = fma2(W2[4],  sp, ac[0]); ac[1] = fma2(W2[5],  sp, ac[1]);
            ac[2] = fma2(W2[6],  sp, ac[2]); ac[3] = fma2(W2[7],  sp, ac[3]);
            sp = pk2(s2, s2);
            ac[0] = fma2(W2[8],  sp, ac[0]); ac[1] = fma2(W2[9],  sp, ac[1]);
            ac[2] = fma2(W2[10], sp, ac[2]); ac[3] = fma2(W2[11], sp, ac[3]);
            sp = pk2(s3, s3);
            ac[0] = fma2(W2[12], sp, ac[0]); ac[1] = fma2(W2[13], sp, ac[1]);
            ac[2] = fma2(W2[14], sp, ac[2]); ac[3] = fma2(W2[15], sp, ac[3]);
        }
    }

    // combine halves and stage
    #pragma unroll
    for (int p = 0; p < 4; p++) {
        float2 a0 = uf2(acc0[p]), a1 = uf2(acc1[p]);
        a0.x += __shfl_xor_sync(0xffffffffu, a0.x, 1);
        a0.y += __shfl_xor_sync(0xffffffffu, a0.y, 1);
        a1.x += __shfl_xor_sync(0xffffffffu, a1.x, 1);
        a1.y += __shfl_xor_sync(0xffffffffu, a1.y, 1);
        if (half == 0) {
            sfeat[(g*8 + 2*p)*SFS + pl]          = a0.x;
            sfeat[(g*8 + 2*p + 1)*SFS + pl]      = a0.y;
            sfeat[(g*8 + 2*p)*SFS + pl + 16]     = a1.x;
            sfeat[(g*8 + 2*p + 1)*SFS + pl + 16] = a1.y;
        }
    }
    __syncthreads();

    #pragma unroll
    for (int it = 0; it < 2; it++) {
        int idx = t + it*256;
        int oc = idx >> 3, p4 = idx & 7;
        float4 f = *(const float4*)(sfeat + oc*SFS + p4*4);
        int base = ((b*CC + oc)*HH + h)*WW + px0 + p4*4;
        float4 at = *(const float4*)(g_atten + base);
        float4 xv = *(const float4*)(x + base);
        float4 ov = make_float4(fmaf(at.x, f.x, xv.x), fmaf(at.y, f.y, xv.y),
                                fmaf(at.z, f.z, xv.z), fmaf(at.w, f.w, xv.w));
        *(float4*)(out + base) = ov;
    }
}

extern "C" void kernel_launch(void* const* d_in, const int* in_sizes, int n_in,
                              void* d_out, int out_size)
{
    const float* x    = (const float*)d_in[0];
    const float* offw = (const float*)d_in[1];
    const float* offb = (const float*)d_in[2];
    const float* pa   = (const float*)d_in[3];
    const float* dw   = (const float*)d_in[4];
    const float* db   = (const float*)d_in[5];
    const float* cw   = (const float*)d_in[6];
    float* out = (float*)d_out;

    const int smemH = 9216 + 16*SWR*8 + 64*SFS*4;   // 37248

    cudaFuncSetAttribute(k_convMMA5, cudaFuncAttributeMaxDynamicSharedMemorySize, SMEM5);
    cudaFuncSetAttribute(k_deformH2, cudaFuncAttributeMaxDynamicSharedMemorySize, smemH);

    k_prepB<<<198, 256>>>(cw, offw);
    k_transpose<<<2048, 256>>>(x);
    k_convMMA5<<<512, 256, SMEM5>>>(offb, pa);
    k_deformH2<<<4096, 256, smemH>>>(x, dw, db, out);   // 4th launch -> ncu capture
}